// round 14
// baseline (speedup 1.0000x reference)
#include <cuda_runtime.h>
#include <mma.h>
#include <math.h>
#include <stdint.h>

using namespace nvcuda;

#define NN   4096
#define DD   256
#define MM   4100
#define RCAP 96
#define NNZCAP 262144

// ---------------- scratch (device globals) ----------------
__device__ __align__(16) float g_deg[MM];
__device__ int   g_row_cnt[NN];
__device__ int   g_row_idx[NN * RCAP];
__device__ __align__(16) float g_row_val[NN * RCAP];
__device__ int   g_col_cnt[MM];
__device__ int   g_col_ptr[MM + 1];
__device__ int   g_col_fill[MM];
__device__ int   g_col_idx[NNZCAP];
__device__ __align__(16) float g_col_val[NNZCAP];

__device__ __align__(16) float g_Xn[NN * DD];
__device__ __align__(16) float g_En[NN * DD];
__device__ __align__(16) float g_q [NN * DD];
__device__ __align__(16) float g_k [MM * DD];
__device__ __align__(16) float g_af[NN * DD];
__device__ __align__(16) float g_X1[NN * DD];
__device__ __align__(16) float g_X2[NN * DD];
__device__ __align__(16) float g_A [NN];
__device__ __align__(16) float g_part[64 * DD];
__device__ __align__(16) float g_epart[4 * 32 * DD];
__device__ float g_pmax[64];
__device__ float g_psum[64];
__device__ int   g_bar1;
__device__ int   g_bar2;

// ---------------- helpers ----------------
__device__ __forceinline__ float warpSum(float v) {
#pragma unroll
    for (int o = 16; o; o >>= 1) v += __shfl_xor_sync(0xffffffffu, v, o);
    return v;
}
__device__ __forceinline__ float warpMax(float v) {
#pragma unroll
    for (int o = 16; o; o >>= 1) v = fmaxf(v, __shfl_xor_sync(0xffffffffu, v, o));
    return v;
}
__device__ __forceinline__ float blockSum256(float v, float* sm) {
    int lane = threadIdx.x & 31, w = threadIdx.x >> 5;
    v = warpSum(v);
    if (lane == 0) sm[w] = v;
    __syncthreads();
    if (threadIdx.x == 0) {
        float s = 0.f;
#pragma unroll
        for (int i = 0; i < 8; i++) s += sm[i];
        sm[0] = s;
    }
    __syncthreads();
    float r = sm[0];
    __syncthreads();
    return r;
}
__device__ __forceinline__ float blockMax256(float v, float* sm) {
    int lane = threadIdx.x & 31, w = threadIdx.x >> 5;
    v = warpMax(v);
    if (lane == 0) sm[w] = v;
    __syncthreads();
    if (threadIdx.x == 0) {
        float s = sm[0];
#pragma unroll
        for (int i = 1; i < 8; i++) s = fmaxf(s, sm[i]);
        sm[0] = s;
    }
    __syncthreads();
    float r = sm[0];
    __syncthreads();
    return r;
}

// ---------------- structure build ----------------
__global__ void init_k() {
    int i = blockIdx.x * blockDim.x + threadIdx.x;
    int st = gridDim.x * blockDim.x;
    for (int j = i; j < MM; j += st) { g_col_cnt[j] = 0; g_deg[j] = 0.f; }
    for (int j = i; j < NN; j += st) g_A[j] = 0.f;
    if (i == 0) { g_bar1 = 0; g_bar2 = 0; }
}

// warp per row; MLP=4: load 4 independent float4 per iteration, then run the
// 4 ordered compaction sub-steps. 8 iterations cover cols [0,4096); tail 4 cols.
__global__ void __launch_bounds__(256) build_rows(const float* __restrict__ H) {
    int warp = (blockIdx.x * blockDim.x + threadIdx.x) >> 5;
    if (warp >= NN) return;
    int lane = threadIdx.x & 31;
    const float4* row4 = (const float4*)(H + (size_t)warp * MM);  // 1025 float4
    int* ri = g_row_idx + (size_t)warp * RCAP;
    float* rv = g_row_val + (size_t)warp * RCAP;
    int base = 0;
#pragma unroll 1
    for (int it = 0; it < 8; it++) {
        float4 v[4];
#pragma unroll
        for (int sub = 0; sub < 4; sub++)
            v[sub] = row4[it * 128 + sub * 32 + lane];
#pragma unroll
        for (int sub = 0; sub < 4; sub++) {
            int colbase = (it * 128 + sub * 32 + lane) * 4;
            int c0 = v[sub].x != 0.f, c1 = v[sub].y != 0.f;
            int c2 = v[sub].z != 0.f, c3 = v[sub].w != 0.f;
            int cnt = c0 + c1 + c2 + c3;
            int inc = cnt;
#pragma unroll
            for (int o = 1; o < 32; o <<= 1) {
                int t = __shfl_up_sync(0xffffffffu, inc, o);
                if (lane >= o) inc += t;
            }
            int tot = __shfl_sync(0xffffffffu, inc, 31);
            int pos = base + inc - cnt;
            if (c0) { ri[pos] = colbase;     rv[pos] = v[sub].x;
                      atomicAdd(&g_col_cnt[colbase], 1);     atomicAdd(&g_deg[colbase], v[sub].x);     pos++; }
            if (c1) { ri[pos] = colbase + 1; rv[pos] = v[sub].y;
                      atomicAdd(&g_col_cnt[colbase + 1], 1); atomicAdd(&g_deg[colbase + 1], v[sub].y); pos++; }
            if (c2) { ri[pos] = colbase + 2; rv[pos] = v[sub].z;
                      atomicAdd(&g_col_cnt[colbase + 2], 1); atomicAdd(&g_deg[colbase + 2], v[sub].z); pos++; }
            if (c3) { ri[pos] = colbase + 3; rv[pos] = v[sub].w;
                      atomicAdd(&g_col_cnt[colbase + 3], 1); atomicAdd(&g_deg[colbase + 3], v[sub].w); pos++; }
            base += tot;
        }
    }
    // tail: float4 #1024 covers cols 4096..4099 (lane 0 only)
    {
        float4 v = (lane == 0) ? row4[1024] : make_float4(0.f, 0.f, 0.f, 0.f);
        int colbase = 4096;
        int c0 = (lane == 0) && (v.x != 0.f), c1 = (lane == 0) && (v.y != 0.f);
        int c2 = (lane == 0) && (v.z != 0.f), c3 = (lane == 0) && (v.w != 0.f);
        int cnt = c0 + c1 + c2 + c3;
        int inc = cnt;
#pragma unroll
        for (int o = 1; o < 32; o <<= 1) {
            int t = __shfl_up_sync(0xffffffffu, inc, o);
            if (lane >= o) inc += t;
        }
        int tot = __shfl_sync(0xffffffffu, inc, 31);
        int pos = base + inc - cnt;
        if (c0) { ri[pos] = colbase;     rv[pos] = v.x;
                  atomicAdd(&g_col_cnt[colbase], 1);     atomicAdd(&g_deg[colbase], v.x);     pos++; }
        if (c1) { ri[pos] = colbase + 1; rv[pos] = v.y;
                  atomicAdd(&g_col_cnt[colbase + 1], 1); atomicAdd(&g_deg[colbase + 1], v.y); pos++; }
        if (c2) { ri[pos] = colbase + 2; rv[pos] = v.z;
                  atomicAdd(&g_col_cnt[colbase + 2], 1); atomicAdd(&g_deg[colbase + 2], v.z); pos++; }
        if (c3) { ri[pos] = colbase + 3; rv[pos] = v.w;
                  atomicAdd(&g_col_cnt[colbase + 3], 1); atomicAdd(&g_deg[colbase + 3], v.w); pos++; }
        base += tot;
    }
    if (lane == 0) g_row_cnt[warp] = base;
}

// hierarchical warp-shuffle scan: 2 barriers
__global__ void scan_cols() {
    __shared__ int warpTot[32];
    __shared__ int warpExcl[32];
    int tid = threadIdx.x, lane = tid & 31, w = tid >> 5;
    int b0 = tid * 5;
    int local[5];
    int s = 0;
#pragma unroll
    for (int j = 0; j < 5; j++) {
        int m = b0 + j;
        int c = (m < MM) ? g_col_cnt[m] : 0;
        local[j] = s; s += c;
    }
    int mysum = s;
#pragma unroll
    for (int o = 1; o < 32; o <<= 1) {
        int t = __shfl_up_sync(0xffffffffu, s, o);
        if (lane >= o) s += t;
    }
    if (lane == 31) warpTot[w] = s;
    __syncthreads();
    if (w == 0) {
        int v = warpTot[lane];
        int inc = v;
#pragma unroll
        for (int o = 1; o < 32; o <<= 1) {
            int t = __shfl_up_sync(0xffffffffu, inc, o);
            if (lane >= o) inc += t;
        }
        warpExcl[lane] = inc - v;
        if (lane == 31) warpTot[0] = inc;   // grand total
    }
    __syncthreads();
    int excl = warpExcl[w] + (s - mysum);
#pragma unroll
    for (int j = 0; j < 5; j++) {
        int m = b0 + j;
        if (m < MM) { g_col_ptr[m] = excl + local[j]; g_col_fill[m] = excl + local[j]; }
    }
    if (tid == 0) g_col_ptr[MM] = warpTot[0];
}

// speculative first-tile load: idx/val for entry `lane` issued concurrently
// with cnt (always within the RCAP-sized row region, so safe).
__global__ void __launch_bounds__(256) fill_cols() {
    int warp = (blockIdx.x * blockDim.x + threadIdx.x) >> 5;
    if (warp >= NN) return;
    int lane = threadIdx.x & 31;
    const int* ri = g_row_idx + (size_t)warp * RCAP;
    const float* rv = g_row_val + (size_t)warp * RCAP;
    int cnt = g_row_cnt[warp];
    int m0 = ri[lane];
    float v0 = rv[lane];
    if (lane < cnt) {
        int p = atomicAdd(&g_col_fill[m0], 1);
        g_col_idx[p] = warp;
        g_col_val[p] = v0;
    }
    for (int j = 32 + lane; j < cnt; j += 32) {
        int m = ri[j];
        float v = rv[j];
        int p = atomicAdd(&g_col_fill[m], 1);
        g_col_idx[p] = warp;
        g_col_val[p] = v;
    }
}

// ---------------- per-layer kernels ----------------
__global__ void ln_rows(const float* __restrict__ X, float* __restrict__ O,
                        const float* __restrict__ g, const float* __restrict__ b) {
    int warp = (blockIdx.x * blockDim.x + threadIdx.x) >> 5;
    if (warp >= NN) return;
    int lane = threadIdx.x & 31;
    const float4* x4 = (const float4*)(X + (size_t)warp * DD);
    float4 v0 = x4[lane], v1 = x4[lane + 32];
    float s = v0.x + v0.y + v0.z + v0.w + v1.x + v1.y + v1.z + v1.w;
    s = warpSum(s);
    float mean = s * (1.f / 256.f);
    float c0x = v0.x - mean, c0y = v0.y - mean, c0z = v0.z - mean, c0w = v0.w - mean;
    float c1x = v1.x - mean, c1y = v1.y - mean, c1z = v1.z - mean, c1w = v1.w - mean;
    float ss = c0x*c0x + c0y*c0y + c0z*c0z + c0w*c0w + c1x*c1x + c1y*c1y + c1z*c1z + c1w*c1w;
    ss = warpSum(ss);
    float rs = rsqrtf(ss * (1.f / 256.f) + 1e-5f);
    const float4* g4 = (const float4*)g;
    const float4* b4 = (const float4*)b;
    float4 G0 = g4[lane], G1 = g4[lane + 32], B0 = b4[lane], B1 = b4[lane + 32];
    float4* o4 = (float4*)(O + (size_t)warp * DD);
    o4[lane]      = make_float4(c0x*rs*G0.x + B0.x, c0y*rs*G0.y + B0.y,
                                c0z*rs*G0.z + B0.z, c0w*rs*G0.w + B0.w);
    o4[lane + 32] = make_float4(c1x*rs*G1.x + B1.x, c1y*rs*G1.y + B1.y,
                                c1z*rs*G1.z + B1.z, c1w*rs*G1.w + B1.w);
}

// blocks [0,128): dense tail partials (long poles -> scheduled FIRST)
// blocks [128,NN+128): sparse edge gather + LN -> g_En (MLP=8 gather)
__global__ void __launch_bounds__(256) egather_all(const float* __restrict__ X,
        const float* __restrict__ g, const float* __restrict__ b) {
    __shared__ int sidx[RCAP];
    __shared__ float sval[RCAP];
    __shared__ float sm[8];
    int bid = blockIdx.x, d = threadIdx.x;
    if (bid >= 128) {
        int m = bid - 128;
        int p0 = g_col_ptr[m], p1 = g_col_ptr[m + 1];
        int cnt = p1 - p0;
        if (d < cnt && d < RCAP) { sidx[d] = g_col_idx[p0 + d]; sval[d] = g_col_val[p0 + d]; }
        __syncthreads();
        float a0 = 0.f, a1 = 0.f, a2 = 0.f, a3 = 0.f;
        float a4 = 0.f, a5 = 0.f, a6 = 0.f, a7 = 0.f;
        int j = 0;
        for (; j + 8 <= cnt; j += 8) {
            int n[8];
#pragma unroll
            for (int t = 0; t < 8; t++) n[t] = sidx[j + t];
            float x[8];
#pragma unroll
            for (int t = 0; t < 8; t++) x[t] = X[(size_t)n[t] * DD + d];
            a0 = fmaf(sval[j],   x[0], a0); a1 = fmaf(sval[j+1], x[1], a1);
            a2 = fmaf(sval[j+2], x[2], a2); a3 = fmaf(sval[j+3], x[3], a3);
            a4 = fmaf(sval[j+4], x[4], a4); a5 = fmaf(sval[j+5], x[5], a5);
            a6 = fmaf(sval[j+6], x[6], a6); a7 = fmaf(sval[j+7], x[7], a7);
        }
        for (; j + 4 <= cnt; j += 4) {
            int n0 = sidx[j], n1 = sidx[j+1], n2 = sidx[j+2], n3 = sidx[j+3];
            float x0 = X[(size_t)n0 * DD + d], x1 = X[(size_t)n1 * DD + d];
            float x2 = X[(size_t)n2 * DD + d], x3 = X[(size_t)n3 * DD + d];
            a0 = fmaf(sval[j],   x0, a0); a1 = fmaf(sval[j+1], x1, a1);
            a2 = fmaf(sval[j+2], x2, a2); a3 = fmaf(sval[j+3], x3, a3);
        }
        for (; j < cnt; j++) a0 = fmaf(sval[j], X[(size_t)sidx[j] * DD + d], a0);
        float acc = (((a0 + a1) + (a2 + a3)) + ((a4 + a5) + (a6 + a7))) / g_deg[m];
        float mean = blockSum256(acc, sm) * (1.f / 256.f);
        float c = acc - mean;
        float var = blockSum256(c * c, sm) * (1.f / 256.f);
        float rs = rsqrtf(var + 1e-5f);
        g_En[(size_t)m * DD + d] = c * rs * g[d] + b[d];
    } else {
        int t = bid;
        int e = t >> 5, slice = t & 31;
        int m = NN + e;
        int p0 = g_col_ptr[m], p1 = g_col_ptr[m + 1];
        int cnt = p1 - p0;
        int per = (cnt + 31) / 32;
        int s0 = p0 + slice * per;
        int s1 = min(s0 + per, p1);
        float a0 = 0.f, a1 = 0.f, a2 = 0.f, a3 = 0.f;
        int p = s0;
        for (; p + 4 <= s1; p += 4) {
            int n0 = g_col_idx[p], n1 = g_col_idx[p+1], n2 = g_col_idx[p+2], n3 = g_col_idx[p+3];
            float w0 = g_col_val[p], w1 = g_col_val[p+1], w2 = g_col_val[p+2], w3 = g_col_val[p+3];
            a0 = fmaf(w0, X[(size_t)n0 * DD + d], a0);
            a1 = fmaf(w1, X[(size_t)n1 * DD + d], a1);
            a2 = fmaf(w2, X[(size_t)n2 * DD + d], a2);
            a3 = fmaf(w3, X[(size_t)n3 * DD + d], a3);
        }
        for (; p < s1; p++) a0 = fmaf(g_col_val[p], X[(size_t)g_col_idx[p] * DD + d], a0);
        g_epart[(size_t)(e * 32 + slice) * DD + d] = (a0 + a1) + (a2 + a3);
    }
}

// 32 blocks: each redundantly reduces dense-tail partials + LN in smem, then
// computes its share of the tail k projections.
__global__ void __launch_bounds__(256) ktail_fin(
        const float* __restrict__ Wkt, const float* __restrict__ bkt,
        const float* __restrict__ Wks, const float* __restrict__ bks,
        const float* __restrict__ g, const float* __restrict__ b) {
    __shared__ __align__(16) float e[4][DD];
    __shared__ float smr[8];
    int tid = threadIdx.x;
#pragma unroll
    for (int r = 0; r < 4; r++) {
        float acc = 0.f;
#pragma unroll
        for (int s = 0; s < 32; s++) acc += g_epart[(size_t)(r * 32 + s) * DD + tid];
        acc /= g_deg[NN + r];
        float mean = blockSum256(acc, smr) * (1.f / 256.f);
        float c = acc - mean;
        float var = blockSum256(c * c, smr) * (1.f / 256.f);
        float rs = rsqrtf(var + 1e-5f);
        e[r][tid] = c * rs * g[tid] + b[tid];
    }
    __syncthreads();
    int w = tid >> 5, lane = tid & 31;
    int gw = blockIdx.x * 8 + w;   // 0..255
    for (int t = gw; t < 4 * DD; t += 256) {
        int r = t >> 8, o = t & 255;
        const float* wrow = ((r < 3) ? Wkt : Wks) + (size_t)o * DD;
        const float4* w4 = (const float4*)wrow;
        const float4* e4 = (const float4*)e[r];
        float4 a = w4[lane], bb = e4[lane];
        float acc = a.x*bb.x + a.y*bb.y + a.z*bb.z + a.w*bb.w;
        float4 a2 = w4[lane + 32], b2 = e4[lane + 32];
        acc += a2.x*b2.x + a2.y*b2.y + a2.z*b2.z + a2.w*b2.w;
        acc = warpSum(acc);
        if (lane == 0) g_k[(size_t)(NN + r) * DD + o] = acc + ((r < 3) ? bkt[o] : bks[o]);
    }
}

// ---------------- tf32 tensor-core GEMM (128x32 tile, 256 blocks, 2/SM) ----------
#define ASTRIDE 40
#define CSTRIDE 68
#define CST2 36
template <int EPI>
__global__ void __launch_bounds__(256) gemm_tc(const float* __restrict__ A,
        const float* __restrict__ W, const float* __restrict__ bias,
        float* __restrict__ C, const float* __restrict__ R) {
    __shared__ __align__(16) float sm[160 * ASTRIDE];   // 25.6 KB
    float* As = sm;                    // 128 x ASTRIDE
    float* Ws = sm + 128 * ASTRIDE;    // 32 x ASTRIDE
    int tid = threadIdx.x;
    int wid = tid >> 5;
    int wr = wid >> 1;      // 0..3 -> rows 32*wr
    int wc = wid & 1;       // 0..1 -> cols 16*wc
    int rowBase = blockIdx.x * 128;
    int colBase = blockIdx.y * 32;

    wmma::fragment<wmma::accumulator, 16, 16, 8, float> acc[2];
    wmma::fill_fragment(acc[0], 0.f);
    wmma::fill_fragment(acc[1], 0.f);

#pragma unroll 1
    for (int k0 = 0; k0 < 256; k0 += 32) {
#pragma unroll
        for (int i = 0; i < 4; i++) {
            int idx = tid + i * 256;
            int row = idx >> 3;
            int c4 = (idx & 7) * 4;
            float4 v = *(const float4*)(A + (size_t)(rowBase + row) * DD + k0 + c4);
            *(float4*)&As[row * ASTRIDE + c4] = v;
        }
        {
            int row = tid >> 3;
            int c4 = (tid & 7) * 4;
            float4 v = *(const float4*)(W + (size_t)(colBase + row) * DD + k0 + c4);
            *(float4*)&Ws[row * ASTRIDE + c4] = v;
        }
        __syncthreads();
#pragma unroll
        for (int kk = 0; kk < 32; kk += 8) {
            wmma::fragment<wmma::matrix_a, 16, 16, 8, wmma::precision::tf32, wmma::row_major> a[2];
            wmma::fragment<wmma::matrix_b, 16, 16, 8, wmma::precision::tf32, wmma::col_major> b;
            wmma::load_matrix_sync(a[0], &As[(wr * 32) * ASTRIDE + kk], ASTRIDE);
            wmma::load_matrix_sync(a[1], &As[(wr * 32 + 16) * ASTRIDE + kk], ASTRIDE);
            wmma::load_matrix_sync(b, &Ws[(wc * 16) * ASTRIDE + kk], ASTRIDE);
#pragma unroll
            for (int t = 0; t < a[0].num_elements; t++) {
                a[0].x[t] = wmma::__float_to_tf32(a[0].x[t]);
                a[1].x[t] = wmma::__float_to_tf32(a[1].x[t]);
            }
#pragma unroll
            for (int t = 0; t < b.num_elements; t++)
                b.x[t] = wmma::__float_to_tf32(b.x[t]);
            wmma::mma_sync(acc[0], a[0], b, acc[0]);
            wmma::mma_sync(acc[1], a[1], b, acc[1]);
        }
        __syncthreads();
    }
    wmma::store_matrix_sync(&sm[(wr * 32) * CST2 + wc * 16],      acc[0], CST2, wmma::mem_row_major);
    wmma::store_matrix_sync(&sm[(wr * 32 + 16) * CST2 + wc * 16], acc[1], CST2, wmma::mem_row_major);
    __syncthreads();

#pragma unroll
    for (int e4 = 0; e4 < 4; e4++) {
        int linear = tid + e4 * 256;      // 0..1023 float4 slots
        int row = linear >> 3;            // 8 float4 per 32-wide row
        int col = (linear & 7) * 4;
        float4 v = *(float4*)&sm[row * CST2 + col];
        float4 bv = *(const float4*)(bias + colBase + col);
        v.x += bv.x; v.y += bv.y; v.z += bv.z; v.w += bv.w;
        int grow = rowBase + row;
        if (EPI == 1) {
            float4 rv = *(const float4*)(R + (size_t)grow * DD + colBase + col);
            v.x = fmaxf(v.x, 0.f) * 0.5f + 0.5f * rv.x;
            v.y = fmaxf(v.y, 0.f) * 0.5f + 0.5f * rv.y;
            v.z = fmaxf(v.z, 0.f) * 0.5f + 0.5f * rv.z;
            v.w = fmaxf(v.w, 0.f) * 0.5f + 0.5f * rv.w;
        }
        *(float4*)(C + (size_t)grow * DD + colBase + col) = v;
    }
}

// Fused gated-attention GEMM: tanh & sigmoid branches for a 128x64 tile,
// reduced through cw directly into g_A via atomics.
__global__ void __launch_bounds__(256) gemm_gated(const float* __restrict__ A,
        const float* __restrict__ Wa, const float* __restrict__ ba,
        const float* __restrict__ Wb, const float* __restrict__ bb_,
        const float* __restrict__ cw) {
    __shared__ __align__(16) float sm[10240];
    float* As  = sm;           // 128 x ASTRIDE
    float* Was = sm + 5120;    // 64 x ASTRIDE
    float* Wbs = sm + 7680;    // 64 x ASTRIDE
    int tid = threadIdx.x;
    int wid = tid >> 5;
    int wr = wid >> 1;
    int wc = wid & 1;
    int rowBase = blockIdx.x * 128;
    int colBase = blockIdx.y * 64;

    wmma::fragment<wmma::accumulator, 16, 16, 8, float> accA[2][2], accB[2][2];
#pragma unroll
    for (int i = 0; i < 2; i++)
#pragma unroll
        for (int j = 0; j < 2; j++) {
            wmma::fill_fragment(accA[i][j], 0.f);
            wmma::fill_fragment(accB[i][j], 0.f);
        }

#pragma unroll 1
    for (int k0 = 0; k0 < 256; k0 += 32) {
#pragma unroll
        for (int i = 0; i < 4; i++) {
            int idx = tid + i * 256;
            int row = idx >> 3;
            int c4 = (idx & 7) * 4;
            float4 v = *(const float4*)(A + (size_t)(rowBase + row) * DD + k0 + c4);
            *(float4*)&As[row * ASTRIDE + c4] = v;
        }
#pragma unroll
        for (int i = 0; i < 2; i++) {
            int idx = tid + i * 256;
            int row = idx >> 3;
            int c4 = (idx & 7) * 4;
            float4 va = *(const float4*)(Wa + (size_t)(colBase + row) * DD + k0 + c4);
            float4 vb = *(const float4*)(Wb + (size_t)(colBase + row) * DD + k0 + c4);
            *(float4*)&Was[row * ASTRIDE + c4] = va;
            *(float4*)&Wbs[row * ASTRIDE + c4] = vb;
        }
        __syncthreads();
#pragma unroll
        for (int kk = 0; kk < 32; kk += 8) {
            wmma::fragment<wmma::matrix_a, 16, 16, 8, wmma::precision::tf32, wmma::row_major> a[2];
            wmma::fragment<wmma::matrix_b, 16, 16, 8, wmma::precision::tf32, wmma::col_major> bA[2], bB[2];
            wmma::load_matrix_sync(a[0], &As[(wr * 32) * ASTRIDE + kk], ASTRIDE);
            wmma::load_matrix_sync(a[1], &As[(wr * 32 + 16) * ASTRIDE + kk], ASTRIDE);
            wmma::load_matrix_sync(bA[0], &Was[(wc * 32) * ASTRIDE + kk], ASTRIDE);
            wmma::load_matrix_sync(bA[1], &Was[(wc * 32 + 16) * ASTRIDE + kk], ASTRIDE);
            wmma::load_matrix_sync(bB[0], &Wbs[(wc * 32) * ASTRIDE + kk], ASTRIDE);
            wmma::load_matrix_sync(bB[1], &Wbs[(wc * 32 + 16) * ASTRIDE + kk], ASTRIDE);
#pragma unroll
            for (int t = 0; t < a[0].num_elements; t++) {
                a[0].x[t] = wmma::__float_to_tf32(a[0].x[t]);
                a[1].x[t] = wmma::__float_to_tf32(a[1].x[t]);
            }
#pragma unroll
            for (int t = 0; t < bA[0].num_elements; t++) {
                bA[0].x[t] = wmma::__float_to_tf32(bA[0].x[t]);
                bA[1].x[t] = wmma::__float_to_tf32(bA[1].x[t]);
                bB[0].x[t] = wmma::__float_to_tf32(bB[0].x[t]);
                bB[1].x[t] = wmma::__float_to_tf32(bB[1].x[t]);
            }
#pragma unroll
            for (int i = 0; i < 2; i++)
#pragma unroll
                for (int j = 0; j < 2; j++) {
                    wmma::mma_sync(accA[i][j], a[i], bA[j], accA[i][j]);
                    wmma::mma_sync(accB[i][j], a[i], bB[j], accB[i][j]);
                }
        }
        __syncthreads();
    }
#pragma unroll
    for (int i = 0; i < 2; i++)
#pragma unroll
        for (int j = 0; j < 2; j++)
            wmma::store_matrix_sync(&sm[(wr * 32 + i * 16) * CSTRIDE + wc * 32 + j * 16],
                                    accA[i][j], CSTRIDE, wmma::mem_row_major);
    __syncthreads();
    float av[8][4];
#pragma unroll
    for (int e4 = 0; e4 < 8; e4++) {
        int linear = tid + e4 * 256;
        int row = linear >> 4;
        int col = (linear & 15) * 4;
        float4 v = *(float4*)&sm[row * CSTRIDE + col];
        float4 bv = *(const float4*)(ba + colBase + col);
        av[e4][0] = tanhf(v.x + bv.x); av[e4][1] = tanhf(v.y + bv.y);
        av[e4][2] = tanhf(v.z + bv.z); av[e4][3] = tanhf(v.w + bv.w);
    }
    __syncthreads();
#pragma unroll
    for (int i = 0; i < 2; i++)
#pragma unroll
        for (int j = 0; j < 2; j++)
            wmma::store_matrix_sync(&sm[(wr * 32 + i * 16) * CSTRIDE + wc * 32 + j * 16],
                                    accB[i][j], CSTRIDE, wmma::mem_row_major);
    __syncthreads();
#pragma unroll
    for (int e4 = 0; e4 < 8; e4++) {
        int linear = tid + e4 * 256;
        int row = linear >> 4;
        int col = (linear & 15) * 4;
        float4 v = *(float4*)&sm[row * CSTRIDE + col];
        float4 bv = *(const float4*)(bb_ + colBase + col);
        float4 cv = *(const float4*)(cw + colBase + col);
        float s0 = 1.f / (1.f + __expf(-(v.x + bv.x)));
        float s1 = 1.f / (1.f + __expf(-(v.y + bv.y)));
        float s2 = 1.f / (1.f + __expf(-(v.z + bv.z)));
        float s3 = 1.f / (1.f + __expf(-(v.w + bv.w)));
        float partial = av[e4][0]*s0*cv.x + av[e4][1]*s1*cv.y
                      + av[e4][2]*s2*cv.z + av[e4][3]*s3*cv.w;
#pragma unroll
        for (int o = 8; o; o >>= 1)
            partial += __shfl_down_sync(0xffffffffu, partial, o, 16);
        if ((tid & 15) == 0) atomicAdd(&g_A[rowBase + row], partial);
    }
}

// sparse masked MHA; block per node, warp per head. Plain softmax (bounded
// scores), 8-edge batches for MLP=8 on the k loads.
__global__ void __launch_bounds__(256) attn_k() {
    int n = blockIdx.x;
    int tid = threadIdx.x;
    int h = tid >> 5, lane = tid & 31;
    __shared__ int sidx[RCAP];
    int cnt = g_row_cnt[n];
    if (tid < cnt) sidx[tid] = g_row_idx[(size_t)n * RCAP + tid];
    __syncthreads();
    int off = h * 32 + lane;
    float qv = g_q[(size_t)n * DD + off];
    float s = 0.f, acc = 0.f;
    const float sc = 0.17677669529663687f;  // 1/sqrt(32)
    for (int j0 = 0; j0 < cnt; j0 += 8) {
        float kv[8], p[8];
#pragma unroll
        for (int t = 0; t < 8; t++) {
            int j = j0 + t;
            int m = sidx[(j < cnt) ? j : 0];
            kv[t] = g_k[(size_t)m * DD + off];
        }
#pragma unroll
        for (int t = 0; t < 8; t++) p[t] = qv * kv[t];
#pragma unroll
        for (int o = 16; o; o >>= 1) {
#pragma unroll
            for (int t = 0; t < 8; t++)
                p[t] += __shfl_xor_sync(0xffffffffu, p[t], o);
        }
#pragma unroll
        for (int t = 0; t < 8; t++) {
            if (j0 + t < cnt) {
                float e = __expf(p[t] * sc);
                s += e;
                acc = fmaf(e, kv[t], acc);
            }
        }
    }
    g_af[(size_t)n * DD + off] = acc / s;
}

// ---------------- fused pooling head (64 blocks, software grid barrier) ---------
__device__ __forceinline__ void gridBar(int* bar, int expected) {
    __syncthreads();
    if (threadIdx.x == 0) {
        __threadfence();
        atomicAdd(bar, 1);
        while (atomicAdd(bar, 0) < expected) { }
    }
    __syncthreads();
}

__global__ void __launch_bounds__(256) pool_all(const float* __restrict__ F,
        const float* __restrict__ ow, const float* __restrict__ ob,
        float* __restrict__ out) {
    __shared__ float sm[8];
    int b = blockIdx.x, tid = threadIdx.x;
    int n0 = b * 64;
    float v = (tid < 64) ? g_A[n0 + tid] : -1e30f;
    float bm = blockMax256(v, sm);
    if (tid == 0) g_pmax[b] = bm;
    gridBar(&g_bar1, 64);
    float pm = (tid < 64) ? g_pmax[tid] : -1e30f;
    float gmax = blockMax256(pm, sm);
    float acc = 0.f;
    for (int j = 0; j < 64; j++) {
        float w = __expf(g_A[n0 + j] - gmax);
        acc = fmaf(w, F[(size_t)(n0 + j) * DD + tid], acc);
    }
    g_part[(size_t)b * DD + tid] = acc;
    float e = (tid < 64) ? __expf(g_A[n0 + tid] - gmax) : 0.f;
    float ps = blockSum256(e, sm);
    if (tid == 0) { g_psum[b] = ps; __threadfence(); }
    gridBar(&g_bar2, 64);
    if (b == 0) {
        __shared__ float pooled[DD];
        float a = 0.f;
        for (int q = 0; q < 64; q++) a += g_part[(size_t)q * DD + tid];
        float pv = (tid < 64) ? g_psum[tid] : 0.f;
        float tot = blockSum256(pv, sm);
        pooled[tid] = a / tot;
        __syncthreads();
        int h = tid >> 5, lane = tid & 31;
        if (h < 4) {
            const float* w = ow + (size_t)h * DD;
            float o = 0.f;
            for (int k2 = lane; k2 < DD; k2 += 32) o = fmaf(pooled[k2], w[k2], o);
            o = warpSum(o);
            if (lane == 0) out[h] = o + ob[h];
        }
    }
}

// ---------------- host orchestration (stream-forked graph) ----------------
struct DevPtrs {
    float *Xn, *En, *q, *k, *af, *X1, *X2;
};

static DevPtrs s_p = {};
static cudaStream_t s_side = 0;
static cudaEvent_t s_evStart, s_evEg1, s_evQK1, s_evX1, s_evEg2, s_evQK2;
static bool s_init = false;

static void one_time_init() {
    if (s_init) return;
    cudaGetSymbolAddress((void**)&s_p.Xn, g_Xn);
    cudaGetSymbolAddress((void**)&s_p.En, g_En);
    cudaGetSymbolAddress((void**)&s_p.q,  g_q);
    cudaGetSymbolAddress((void**)&s_p.k,  g_k);
    cudaGetSymbolAddress((void**)&s_p.af, g_af);
    cudaGetSymbolAddress((void**)&s_p.X1, g_X1);
    cudaGetSymbolAddress((void**)&s_p.X2, g_X2);
    cudaStreamCreateWithFlags(&s_side, cudaStreamNonBlocking);
    cudaEventCreateWithFlags(&s_evStart, cudaEventDisableTiming);
    cudaEventCreateWithFlags(&s_evEg1,   cudaEventDisableTiming);
    cudaEventCreateWithFlags(&s_evQK1,   cudaEventDisableTiming);
    cudaEventCreateWithFlags(&s_evX1,    cudaEventDisableTiming);
    cudaEventCreateWithFlags(&s_evEg2,   cudaEventDisableTiming);
    cudaEventCreateWithFlags(&s_evQK2,   cudaEventDisableTiming);
    s_init = true;
}

extern "C" void kernel_launch(void* const* d_in, const int* in_sizes, int n_in,
                              void* d_out, int out_size) {
    (void)in_sizes; (void)n_in; (void)out_size;
    const float* X     = (const float*)d_in[0];
    const float* H     = (const float*)d_in[1];
    const float* Wq_w  = (const float*)d_in[2];
    const float* Wq_b  = (const float*)d_in[3];
    const float* Wkn_w = (const float*)d_in[4];
    const float* Wkn_b = (const float*)d_in[5];
    const float* Wkt_w = (const float*)d_in[6];
    const float* Wkt_b = (const float*)d_in[7];
    const float* Wks_w = (const float*)d_in[8];
    const float* Wks_b = (const float*)d_in[9];
    const float* fc_w  = (const float*)d_in[10];
    const float* fc_b  = (const float*)d_in[11];
    const float* ln_g  = (const float*)d_in[12];
    const float* ln_b  = (const float*)d_in[13];
    const float* aw    = (const float*)d_in[14];
    const float* ab    = (const float*)d_in[15];
    const float* bw    = (const float*)d_in[16];
    const float* bb    = (const float*)d_in[17];
    const float* cw    = (const float*)d_in[18];
    const float* out_w = (const float*)d_in[20];
    const float* out_b = (const float*)d_in[21];
    float* out = (float*)d_out;

    one_time_init();
    const DevPtrs& p = s_p;
    const int WOFF = DD * DD;
    dim3 grid(32, 8);   // 128x32 tiles -> 256 blocks -> 2/SM

    // fork side stream off the capture-origin (default) stream
    cudaEventRecord(s_evStart, 0);
    cudaStreamWaitEvent(s_side, s_evStart, 0);

    // ---- main: structure build (needs only H) ----
    init_k<<<32, 256>>>();
    build_rows<<<512, 256>>>(H);
    scan_cols<<<1, 1024>>>();
    fill_cols<<<512, 256>>>();

    // ---- side: layer-1 q path (needs only X) ----
    ln_rows<<<512, 256, 0, s_side>>>(X, p.Xn, ln_g, ln_b);
    gemm_tc<0><<<grid, 256, 0, s_side>>>(p.Xn, Wq_w, Wq_b, p.q, nullptr);

    // ---- main: layer-1 edge path ----
    egather_all<<<NN + 128, 256>>>(X, ln_g, ln_b);
    cudaEventRecord(s_evEg1, 0);
    gemm_tc<0><<<grid, 256>>>(p.En, Wkn_w, Wkn_b, p.k, nullptr);

    // ---- side: ktail after egather partials ----
    cudaStreamWaitEvent(s_side, s_evEg1, 0);
    ktail_fin<<<32, 256, 0, s_side>>>(Wkt_w, Wkt_b, Wks_w, Wks_b, ln_g, ln_b);
    cudaEventRecord(s_evQK1, s_side);

    // ---- main: join, attention, fc ----
    cudaStreamWaitEvent(0, s_evQK1, 0);
    attn_k<<<NN, 256>>>();
    gemm_tc<1><<<grid, 256>>>(p.af, fc_w, fc_b, p.X1, X);
    cudaEventRecord(s_evX1, 0);

    // ---- side: layer-2 q path ----
    cudaStreamWaitEvent(s_side, s_evX1, 0);
    ln_rows<<<512, 256, 0, s_side>>>(p.X1, p.Xn, ln_g + DD, ln_b + DD);
    gemm_tc<0><<<grid, 256, 0, s_side>>>(p.Xn, Wq_w + WOFF, Wq_b + DD, p.q, nullptr);

    // ---- main: layer-2 edge path ----
    egather_all<<<NN + 128, 256>>>(p.X1, ln_g + DD, ln_b + DD);
    cudaEventRecord(s_evEg2, 0);
    gemm_tc<0><<<grid, 256>>>(p.En, Wkn_w + WOFF, Wkn_b + DD, p.k, nullptr);

    cudaStreamWaitEvent(s_side, s_evEg2, 0);
    ktail_fin<<<32, 256, 0, s_side>>>(Wkt_w + WOFF, Wkt_b + DD,
                                      Wks_w + WOFF, Wks_b + DD,
                                      ln_g + DD, ln_b + DD);
    cudaEventRecord(s_evQK2, s_side);

    cudaStreamWaitEvent(0, s_evQK2, 0);
    attn_k<<<NN, 256>>>();
    gemm_tc<1><<<grid, 256>>>(p.af, fc_w + WOFF, fc_b + DD, p.X2, p.X1);

    // ---- pooling head ----
    gemm_gated<<<dim3(32, 4), 256>>>(p.X2, aw, ab, bw, bb, cw);
    pool_all<<<64, 256>>>(p.X2, out_w, out_b, out);
}

// round 15
// speedup vs baseline: 1.0262x; 1.0262x over previous
#include <cuda_runtime.h>
#include <mma.h>
#include <math.h>
#include <stdint.h>

using namespace nvcuda;

#define NN   4096
#define DD   256
#define MM   4100
#define RCAP 96
#define CCAP 96          // bucket capacity per sparse column
#define TCAP 2560        // bucket capacity per dense tail column
#define TBASE (NN * CCAP)

// ---------------- scratch (device globals) ----------------
__device__ __align__(16) float g_deg[MM];
__device__ int   g_row_cnt[NN];
__device__ int   g_row_idx[NN * RCAP];
__device__ __align__(16) float g_row_val[NN * RCAP];
__device__ int   g_col_fill[MM];
__device__ int   g_col_idx[NN * CCAP + 4 * TCAP];
__device__ __align__(16) float g_col_val[NN * CCAP + 4 * TCAP];

__device__ __align__(16) float g_Xn[NN * DD];
__device__ __align__(16) float g_En[NN * DD];
__device__ __align__(16) float g_q [NN * DD];
__device__ __align__(16) float g_k [MM * DD];
__device__ __align__(16) float g_af[NN * DD];
__device__ __align__(16) float g_X1[NN * DD];
__device__ __align__(16) float g_X2[NN * DD];
__device__ __align__(16) float g_A [NN];
__device__ __align__(16) float g_part[64 * DD];
__device__ __align__(16) float g_epart[4 * 32 * DD];
__device__ float g_pmax[64];
__device__ float g_psum[64];
__device__ int   g_bar1;
__device__ int   g_bar2;

// ---------------- helpers ----------------
__device__ __forceinline__ float warpSum(float v) {
#pragma unroll
    for (int o = 16; o; o >>= 1) v += __shfl_xor_sync(0xffffffffu, v, o);
    return v;
}
__device__ __forceinline__ float warpMax(float v) {
#pragma unroll
    for (int o = 16; o; o >>= 1) v = fmaxf(v, __shfl_xor_sync(0xffffffffu, v, o));
    return v;
}
__device__ __forceinline__ float blockSum256(float v, float* sm) {
    int lane = threadIdx.x & 31, w = threadIdx.x >> 5;
    v = warpSum(v);
    if (lane == 0) sm[w] = v;
    __syncthreads();
    if (threadIdx.x == 0) {
        float s = 0.f;
#pragma unroll
        for (int i = 0; i < 8; i++) s += sm[i];
        sm[0] = s;
    }
    __syncthreads();
    float r = sm[0];
    __syncthreads();
    return r;
}
__device__ __forceinline__ float blockMax256(float v, float* sm) {
    int lane = threadIdx.x & 31, w = threadIdx.x >> 5;
    v = warpMax(v);
    if (lane == 0) sm[w] = v;
    __syncthreads();
    if (threadIdx.x == 0) {
        float s = sm[0];
#pragma unroll
        for (int i = 1; i < 8; i++) s = fmaxf(s, sm[i]);
        sm[0] = s;
    }
    __syncthreads();
    float r = sm[0];
    __syncthreads();
    return r;
}

__device__ __forceinline__ int bucketBase(int m) {
    return (m < NN) ? m * CCAP : TBASE + (m - NN) * TCAP;
}
__device__ __forceinline__ int bucketCap(int m) {
    return (m < NN) ? CCAP : TCAP;
}

// ---------------- structure build ----------------
__global__ void init_k() {
    int i = blockIdx.x * blockDim.x + threadIdx.x;
    int st = gridDim.x * blockDim.x;
    for (int j = i; j < MM; j += st) { g_col_fill[j] = 0; g_deg[j] = 0.f; }
    for (int j = i; j < NN; j += st) g_A[j] = 0.f;
    if (i == 0) { g_bar1 = 0; g_bar2 = 0; }
}

// warp per row; MLP=4 loads. Builds ordered row lists AND scatters nonzeros
// directly into the bucketed CSC (slot = atomicAdd on fill) in ONE pass over H.
__device__ __forceinline__ void scatterNZ(int m, int warp, float v,
                                          int* ri, float* rv, int pos) {
    ri[pos] = m; rv[pos] = v;
    atomicAdd(&g_deg[m], v);
    int p = atomicAdd(&g_col_fill[m], 1);
    if (p < bucketCap(m)) {
        int o = bucketBase(m) + p;
        g_col_idx[o] = warp;
        g_col_val[o] = v;
    }
}

__global__ void __launch_bounds__(256) build_rows(const float* __restrict__ H) {
    int warp = (blockIdx.x * blockDim.x + threadIdx.x) >> 5;
    if (warp >= NN) return;
    int lane = threadIdx.x & 31;
    const float4* row4 = (const float4*)(H + (size_t)warp * MM);  // 1025 float4
    int* ri = g_row_idx + (size_t)warp * RCAP;
    float* rv = g_row_val + (size_t)warp * RCAP;
    int base = 0;
#pragma unroll 1
    for (int it = 0; it < 8; it++) {
        float4 v[4];
#pragma unroll
        for (int sub = 0; sub < 4; sub++)
            v[sub] = row4[it * 128 + sub * 32 + lane];
#pragma unroll
        for (int sub = 0; sub < 4; sub++) {
            int colbase = (it * 128 + sub * 32 + lane) * 4;
            int c0 = v[sub].x != 0.f, c1 = v[sub].y != 0.f;
            int c2 = v[sub].z != 0.f, c3 = v[sub].w != 0.f;
            int cnt = c0 + c1 + c2 + c3;
            int inc = cnt;
#pragma unroll
            for (int o = 1; o < 32; o <<= 1) {
                int t = __shfl_up_sync(0xffffffffu, inc, o);
                if (lane >= o) inc += t;
            }
            int tot = __shfl_sync(0xffffffffu, inc, 31);
            int pos = base + inc - cnt;
            if (c0) { scatterNZ(colbase,     warp, v[sub].x, ri, rv, pos); pos++; }
            if (c1) { scatterNZ(colbase + 1, warp, v[sub].y, ri, rv, pos); pos++; }
            if (c2) { scatterNZ(colbase + 2, warp, v[sub].z, ri, rv, pos); pos++; }
            if (c3) { scatterNZ(colbase + 3, warp, v[sub].w, ri, rv, pos); pos++; }
            base += tot;
        }
    }
    // tail: float4 #1024 covers cols 4096..4099 (lane 0 only)
    {
        float4 v = (lane == 0) ? row4[1024] : make_float4(0.f, 0.f, 0.f, 0.f);
        int colbase = 4096;
        int c0 = (lane == 0) && (v.x != 0.f), c1 = (lane == 0) && (v.y != 0.f);
        int c2 = (lane == 0) && (v.z != 0.f), c3 = (lane == 0) && (v.w != 0.f);
        int cnt = c0 + c1 + c2 + c3;
        int inc = cnt;
#pragma unroll
        for (int o = 1; o < 32; o <<= 1) {
            int t = __shfl_up_sync(0xffffffffu, inc, o);
            if (lane >= o) inc += t;
        }
        int tot = __shfl_sync(0xffffffffu, inc, 31);
        int pos = base + inc - cnt;
        if (c0) { scatterNZ(colbase,     warp, v.x, ri, rv, pos); pos++; }
        if (c1) { scatterNZ(colbase + 1, warp, v.y, ri, rv, pos); pos++; }
        if (c2) { scatterNZ(colbase + 2, warp, v.z, ri, rv, pos); pos++; }
        if (c3) { scatterNZ(colbase + 3, warp, v.w, ri, rv, pos); pos++; }
        base += tot;
    }
    if (lane == 0) g_row_cnt[warp] = base;
}

// ---------------- per-layer kernels ----------------
__global__ void ln_rows(const float* __restrict__ X, float* __restrict__ O,
                        const float* __restrict__ g, const float* __restrict__ b) {
    int warp = (blockIdx.x * blockDim.x + threadIdx.x) >> 5;
    if (warp >= NN) return;
    int lane = threadIdx.x & 31;
    const float4* x4 = (const float4*)(X + (size_t)warp * DD);
    float4 v0 = x4[lane], v1 = x4[lane + 32];
    float s = v0.x + v0.y + v0.z + v0.w + v1.x + v1.y + v1.z + v1.w;
    s = warpSum(s);
    float mean = s * (1.f / 256.f);
    float c0x = v0.x - mean, c0y = v0.y - mean, c0z = v0.z - mean, c0w = v0.w - mean;
    float c1x = v1.x - mean, c1y = v1.y - mean, c1z = v1.z - mean, c1w = v1.w - mean;
    float ss = c0x*c0x + c0y*c0y + c0z*c0z + c0w*c0w + c1x*c1x + c1y*c1y + c1z*c1z + c1w*c1w;
    ss = warpSum(ss);
    float rs = rsqrtf(ss * (1.f / 256.f) + 1e-5f);
    const float4* g4 = (const float4*)g;
    const float4* b4 = (const float4*)b;
    float4 G0 = g4[lane], G1 = g4[lane + 32], B0 = b4[lane], B1 = b4[lane + 32];
    float4* o4 = (float4*)(O + (size_t)warp * DD);
    o4[lane]      = make_float4(c0x*rs*G0.x + B0.x, c0y*rs*G0.y + B0.y,
                                c0z*rs*G0.z + B0.z, c0w*rs*G0.w + B0.w);
    o4[lane + 32] = make_float4(c1x*rs*G1.x + B1.x, c1y*rs*G1.y + B1.y,
                                c1z*rs*G1.z + B1.z, c1w*rs*G1.w + B1.w);
}

// blocks [0,128): dense tail partials (long poles -> scheduled FIRST)
// blocks [128,NN+128): sparse edge gather + LN -> g_En  (bucketed CSC)
__global__ void __launch_bounds__(256) egather_all(const float* __restrict__ X,
        const float* __restrict__ g, const float* __restrict__ b) {
    __shared__ int sidx[CCAP];
    __shared__ float sval[CCAP];
    __shared__ float sm[8];
    int bid = blockIdx.x, d = threadIdx.x;
    if (bid >= 128) {
        int m = bid - 128;
        int p0 = m * CCAP;
        int cnt = min(g_col_fill[m], CCAP);
        if (d < cnt) { sidx[d] = g_col_idx[p0 + d]; sval[d] = g_col_val[p0 + d]; }
        __syncthreads();
        float a0 = 0.f, a1 = 0.f, a2 = 0.f, a3 = 0.f;
        int j = 0;
        for (; j + 4 <= cnt; j += 4) {
            int n0 = sidx[j], n1 = sidx[j+1], n2 = sidx[j+2], n3 = sidx[j+3];
            float x0 = X[(size_t)n0 * DD + d], x1 = X[(size_t)n1 * DD + d];
            float x2 = X[(size_t)n2 * DD + d], x3 = X[(size_t)n3 * DD + d];
            a0 = fmaf(sval[j],   x0, a0); a1 = fmaf(sval[j+1], x1, a1);
            a2 = fmaf(sval[j+2], x2, a2); a3 = fmaf(sval[j+3], x3, a3);
        }
        for (; j < cnt; j++) a0 = fmaf(sval[j], X[(size_t)sidx[j] * DD + d], a0);
        float acc = ((a0 + a1) + (a2 + a3)) / g_deg[m];
        float mean = blockSum256(acc, sm) * (1.f / 256.f);
        float c = acc - mean;
        float var = blockSum256(c * c, sm) * (1.f / 256.f);
        float rs = rsqrtf(var + 1e-5f);
        g_En[(size_t)m * DD + d] = c * rs * g[d] + b[d];
    } else {
        int t = bid;
        int e = t >> 5, slice = t & 31;
        int m = NN + e;
        int p0 = TBASE + e * TCAP;
        int cnt = min(g_col_fill[m], TCAP);
        int per = (cnt + 31) / 32;
        int s0 = p0 + slice * per;
        int s1 = min(s0 + per, p0 + cnt);
        float a0 = 0.f, a1 = 0.f, a2 = 0.f, a3 = 0.f;
        int p = s0;
        for (; p + 4 <= s1; p += 4) {
            int n0 = g_col_idx[p], n1 = g_col_idx[p+1], n2 = g_col_idx[p+2], n3 = g_col_idx[p+3];
            float w0 = g_col_val[p], w1 = g_col_val[p+1], w2 = g_col_val[p+2], w3 = g_col_val[p+3];
            a0 = fmaf(w0, X[(size_t)n0 * DD + d], a0);
            a1 = fmaf(w1, X[(size_t)n1 * DD + d], a1);
            a2 = fmaf(w2, X[(size_t)n2 * DD + d], a2);
            a3 = fmaf(w3, X[(size_t)n3 * DD + d], a3);
        }
        for (; p < s1; p++) a0 = fmaf(g_col_val[p], X[(size_t)g_col_idx[p] * DD + d], a0);
        g_epart[(size_t)(e * 32 + slice) * DD + d] = (a0 + a1) + (a2 + a3);
    }
}

// 32 blocks: each redundantly reduces dense-tail partials + LN in smem, then
// computes its share of the tail k projections.
__global__ void __launch_bounds__(256) ktail_fin(
        const float* __restrict__ Wkt, const float* __restrict__ bkt,
        const float* __restrict__ Wks, const float* __restrict__ bks,
        const float* __restrict__ g, const float* __restrict__ b) {
    __shared__ __align__(16) float e[4][DD];
    __shared__ float smr[8];
    int tid = threadIdx.x;
#pragma unroll
    for (int r = 0; r < 4; r++) {
        float acc = 0.f;
#pragma unroll
        for (int s = 0; s < 32; s++) acc += g_epart[(size_t)(r * 32 + s) * DD + tid];
        acc /= g_deg[NN + r];
        float mean = blockSum256(acc, smr) * (1.f / 256.f);
        float c = acc - mean;
        float var = blockSum256(c * c, smr) * (1.f / 256.f);
        float rs = rsqrtf(var + 1e-5f);
        e[r][tid] = c * rs * g[tid] + b[tid];
    }
    __syncthreads();
    int w = tid >> 5, lane = tid & 31;
    int gw = blockIdx.x * 8 + w;   // 0..255
    for (int t = gw; t < 4 * DD; t += 256) {
        int r = t >> 8, o = t & 255;
        const float* wrow = ((r < 3) ? Wkt : Wks) + (size_t)o * DD;
        const float4* w4 = (const float4*)wrow;
        const float4* e4 = (const float4*)e[r];
        float4 a = w4[lane], bb = e4[lane];
        float acc = a.x*bb.x + a.y*bb.y + a.z*bb.z + a.w*bb.w;
        float4 a2 = w4[lane + 32], b2 = e4[lane + 32];
        acc += a2.x*b2.x + a2.y*b2.y + a2.z*b2.z + a2.w*b2.w;
        acc = warpSum(acc);
        if (lane == 0) g_k[(size_t)(NN + r) * DD + o] = acc + ((r < 3) ? bkt[o] : bks[o]);
    }
}

// ---------------- tf32 tensor-core GEMM (128x32 tile, 256 blocks, 2/SM) ----------
#define ASTRIDE 40
#define CSTRIDE 68
#define CST2 36
template <int EPI>
__global__ void __launch_bounds__(256) gemm_tc(const float* __restrict__ A,
        const float* __restrict__ W, const float* __restrict__ bias,
        float* __restrict__ C, const float* __restrict__ R) {
    __shared__ __align__(16) float sm[160 * ASTRIDE];   // 25.6 KB
    float* As = sm;                    // 128 x ASTRIDE
    float* Ws = sm + 128 * ASTRIDE;    // 32 x ASTRIDE
    int tid = threadIdx.x;
    int wid = tid >> 5;
    int wr = wid >> 1;      // 0..3 -> rows 32*wr
    int wc = wid & 1;       // 0..1 -> cols 16*wc
    int rowBase = blockIdx.x * 128;
    int colBase = blockIdx.y * 32;

    wmma::fragment<wmma::accumulator, 16, 16, 8, float> acc[2];
    wmma::fill_fragment(acc[0], 0.f);
    wmma::fill_fragment(acc[1], 0.f);

#pragma unroll 1
    for (int k0 = 0; k0 < 256; k0 += 32) {
#pragma unroll
        for (int i = 0; i < 4; i++) {
            int idx = tid + i * 256;
            int row = idx >> 3;
            int c4 = (idx & 7) * 4;
            float4 v = *(const float4*)(A + (size_t)(rowBase + row) * DD + k0 + c4);
            *(float4*)&As[row * ASTRIDE + c4] = v;
        }
        {
            int row = tid >> 3;
            int c4 = (tid & 7) * 4;
            float4 v = *(const float4*)(W + (size_t)(colBase + row) * DD + k0 + c4);
            *(float4*)&Ws[row * ASTRIDE + c4] = v;
        }
        __syncthreads();
#pragma unroll
        for (int kk = 0; kk < 32; kk += 8) {
            wmma::fragment<wmma::matrix_a, 16, 16, 8, wmma::precision::tf32, wmma::row_major> a[2];
            wmma::fragment<wmma::matrix_b, 16, 16, 8, wmma::precision::tf32, wmma::col_major> b;
            wmma::load_matrix_sync(a[0], &As[(wr * 32) * ASTRIDE + kk], ASTRIDE);
            wmma::load_matrix_sync(a[1], &As[(wr * 32 + 16) * ASTRIDE + kk], ASTRIDE);
            wmma::load_matrix_sync(b, &Ws[(wc * 16) * ASTRIDE + kk], ASTRIDE);
#pragma unroll
            for (int t = 0; t < a[0].num_elements; t++) {
                a[0].x[t] = wmma::__float_to_tf32(a[0].x[t]);
                a[1].x[t] = wmma::__float_to_tf32(a[1].x[t]);
            }
#pragma unroll
            for (int t = 0; t < b.num_elements; t++)
                b.x[t] = wmma::__float_to_tf32(b.x[t]);
            wmma::mma_sync(acc[0], a[0], b, acc[0]);
            wmma::mma_sync(acc[1], a[1], b, acc[1]);
        }
        __syncthreads();
    }
    wmma::store_matrix_sync(&sm[(wr * 32) * CST2 + wc * 16],      acc[0], CST2, wmma::mem_row_major);
    wmma::store_matrix_sync(&sm[(wr * 32 + 16) * CST2 + wc * 16], acc[1], CST2, wmma::mem_row_major);
    __syncthreads();

#pragma unroll
    for (int e4 = 0; e4 < 4; e4++) {
        int linear = tid + e4 * 256;      // 0..1023 float4 slots
        int row = linear >> 3;            // 8 float4 per 32-wide row
        int col = (linear & 7) * 4;
        float4 v = *(float4*)&sm[row * CST2 + col];
        float4 bv = *(const float4*)(bias + colBase + col);
        v.x += bv.x; v.y += bv.y; v.z += bv.z; v.w += bv.w;
        int grow = rowBase + row;
        if (EPI == 1) {
            float4 rv = *(const float4*)(R + (size_t)grow * DD + colBase + col);
            v.x = fmaxf(v.x, 0.f) * 0.5f + 0.5f * rv.x;
            v.y = fmaxf(v.y, 0.f) * 0.5f + 0.5f * rv.y;
            v.z = fmaxf(v.z, 0.f) * 0.5f + 0.5f * rv.z;
            v.w = fmaxf(v.w, 0.f) * 0.5f + 0.5f * rv.w;
        }
        *(float4*)(C + (size_t)grow * DD + colBase + col) = v;
    }
}

// Fused gated-attention GEMM: tanh & sigmoid branches for a 128x64 tile,
// reduced through cw directly into g_A via atomics.
__global__ void __launch_bounds__(256) gemm_gated(const float* __restrict__ A,
        const float* __restrict__ Wa, const float* __restrict__ ba,
        const float* __restrict__ Wb, const float* __restrict__ bb_,
        const float* __restrict__ cw) {
    __shared__ __align__(16) float sm[10240];
    float* As  = sm;           // 128 x ASTRIDE
    float* Was = sm + 5120;    // 64 x ASTRIDE
    float* Wbs = sm + 7680;    // 64 x ASTRIDE
    int tid = threadIdx.x;
    int wid = tid >> 5;
    int wr = wid >> 1;
    int wc = wid & 1;
    int rowBase = blockIdx.x * 128;
    int colBase = blockIdx.y * 64;

    wmma::fragment<wmma::accumulator, 16, 16, 8, float> accA[2][2], accB[2][2];
#pragma unroll
    for (int i = 0; i < 2; i++)
#pragma unroll
        for (int j = 0; j < 2; j++) {
            wmma::fill_fragment(accA[i][j], 0.f);
            wmma::fill_fragment(accB[i][j], 0.f);
        }

#pragma unroll 1
    for (int k0 = 0; k0 < 256; k0 += 32) {
#pragma unroll
        for (int i = 0; i < 4; i++) {
            int idx = tid + i * 256;
            int row = idx >> 3;
            int c4 = (idx & 7) * 4;
            float4 v = *(const float4*)(A + (size_t)(rowBase + row) * DD + k0 + c4);
            *(float4*)&As[row * ASTRIDE + c4] = v;
        }
#pragma unroll
        for (int i = 0; i < 2; i++) {
            int idx = tid + i * 256;
            int row = idx >> 3;
            int c4 = (idx & 7) * 4;
            float4 va = *(const float4*)(Wa + (size_t)(colBase + row) * DD + k0 + c4);
            float4 vb = *(const float4*)(Wb + (size_t)(colBase + row) * DD + k0 + c4);
            *(float4*)&Was[row * ASTRIDE + c4] = va;
            *(float4*)&Wbs[row * ASTRIDE + c4] = vb;
        }
        __syncthreads();
#pragma unroll
        for (int kk = 0; kk < 32; kk += 8) {
            wmma::fragment<wmma::matrix_a, 16, 16, 8, wmma::precision::tf32, wmma::row_major> a[2];
            wmma::fragment<wmma::matrix_b, 16, 16, 8, wmma::precision::tf32, wmma::col_major> bA[2], bB[2];
            wmma::load_matrix_sync(a[0], &As[(wr * 32) * ASTRIDE + kk], ASTRIDE);
            wmma::load_matrix_sync(a[1], &As[(wr * 32 + 16) * ASTRIDE + kk], ASTRIDE);
            wmma::load_matrix_sync(bA[0], &Was[(wc * 32) * ASTRIDE + kk], ASTRIDE);
            wmma::load_matrix_sync(bA[1], &Was[(wc * 32 + 16) * ASTRIDE + kk], ASTRIDE);
            wmma::load_matrix_sync(bB[0], &Wbs[(wc * 32) * ASTRIDE + kk], ASTRIDE);
            wmma::load_matrix_sync(bB[1], &Wbs[(wc * 32 + 16) * ASTRIDE + kk], ASTRIDE);
#pragma unroll
            for (int t = 0; t < a[0].num_elements; t++) {
                a[0].x[t] = wmma::__float_to_tf32(a[0].x[t]);
                a[1].x[t] = wmma::__float_to_tf32(a[1].x[t]);
            }
#pragma unroll
            for (int t = 0; t < bA[0].num_elements; t++) {
                bA[0].x[t] = wmma::__float_to_tf32(bA[0].x[t]);
                bA[1].x[t] = wmma::__float_to_tf32(bA[1].x[t]);
                bB[0].x[t] = wmma::__float_to_tf32(bB[0].x[t]);
                bB[1].x[t] = wmma::__float_to_tf32(bB[1].x[t]);
            }
#pragma unroll
            for (int i = 0; i < 2; i++)
#pragma unroll
                for (int j = 0; j < 2; j++) {
                    wmma::mma_sync(accA[i][j], a[i], bA[j], accA[i][j]);
                    wmma::mma_sync(accB[i][j], a[i], bB[j], accB[i][j]);
                }
        }
        __syncthreads();
    }
#pragma unroll
    for (int i = 0; i < 2; i++)
#pragma unroll
        for (int j = 0; j < 2; j++)
            wmma::store_matrix_sync(&sm[(wr * 32 + i * 16) * CSTRIDE + wc * 32 + j * 16],
                                    accA[i][j], CSTRIDE, wmma::mem_row_major);
    __syncthreads();
    float av[8][4];
#pragma unroll
    for (int e4 = 0; e4 < 8; e4++) {
        int linear = tid + e4 * 256;
        int row = linear >> 4;
        int col = (linear & 15) * 4;
        float4 v = *(float4*)&sm[row * CSTRIDE + col];
        float4 bv = *(const float4*)(ba + colBase + col);
        av[e4][0] = tanhf(v.x + bv.x); av[e4][1] = tanhf(v.y + bv.y);
        av[e4][2] = tanhf(v.z + bv.z); av[e4][3] = tanhf(v.w + bv.w);
    }
    __syncthreads();
#pragma unroll
    for (int i = 0; i < 2; i++)
#pragma unroll
        for (int j = 0; j < 2; j++)
            wmma::store_matrix_sync(&sm[(wr * 32 + i * 16) * CSTRIDE + wc * 32 + j * 16],
                                    accB[i][j], CSTRIDE, wmma::mem_row_major);
    __syncthreads();
#pragma unroll
    for (int e4 = 0; e4 < 8; e4++) {
        int linear = tid + e4 * 256;
        int row = linear >> 4;
        int col = (linear & 15) * 4;
        float4 v = *(float4*)&sm[row * CSTRIDE + col];
        float4 bv = *(const float4*)(bb_ + colBase + col);
        float4 cv = *(const float4*)(cw + colBase + col);
        float s0 = 1.f / (1.f + __expf(-(v.x + bv.x)));
        float s1 = 1.f / (1.f + __expf(-(v.y + bv.y)));
        float s2 = 1.f / (1.f + __expf(-(v.z + bv.z)));
        float s3 = 1.f / (1.f + __expf(-(v.w + bv.w)));
        float partial = av[e4][0]*s0*cv.x + av[e4][1]*s1*cv.y
                      + av[e4][2]*s2*cv.z + av[e4][3]*s3*cv.w;
#pragma unroll
        for (int o = 8; o; o >>= 1)
            partial += __shfl_down_sync(0xffffffffu, partial, o, 16);
        if ((tid & 15) == 0) atomicAdd(&g_A[rowBase + row], partial);
    }
}

// sparse masked MHA; block per node, warp per head. Plain softmax (bounded scores).
__global__ void __launch_bounds__(256) attn_k() {
    int n = blockIdx.x;
    int tid = threadIdx.x;
    int h = tid >> 5, lane = tid & 31;
    __shared__ int sidx[RCAP];
    int cnt = g_row_cnt[n];
    if (tid < cnt) sidx[tid] = g_row_idx[(size_t)n * RCAP + tid];
    __syncthreads();
    int off = h * 32 + lane;
    float qv = g_q[(size_t)n * DD + off];
    float s = 0.f, acc = 0.f;
    const float sc = 0.17677669529663687f;  // 1/sqrt(32)
    for (int j0 = 0; j0 < cnt; j0 += 4) {
        int c = cnt - j0;
        float kv0 = g_k[(size_t)sidx[j0] * DD + off];
        float kv1 = (c > 1) ? g_k[(size_t)sidx[j0+1] * DD + off] : 0.f;
        float kv2 = (c > 2) ? g_k[(size_t)sidx[j0+2] * DD + off] : 0.f;
        float kv3 = (c > 3) ? g_k[(size_t)sidx[j0+3] * DD + off] : 0.f;
        float p0 = qv * kv0, p1 = qv * kv1, p2 = qv * kv2, p3 = qv * kv3;
#pragma unroll
        for (int o = 16; o; o >>= 1) {
            p0 += __shfl_xor_sync(0xffffffffu, p0, o);
            p1 += __shfl_xor_sync(0xffffffffu, p1, o);
            p2 += __shfl_xor_sync(0xffffffffu, p2, o);
            p3 += __shfl_xor_sync(0xffffffffu, p3, o);
        }
        float e0 = __expf(p0 * sc);
        float e1 = __expf(p1 * sc);
        float e2 = __expf(p2 * sc);
        float e3 = __expf(p3 * sc);
        s += e0;               acc = fmaf(e0, kv0, acc);
        if (c > 1) { s += e1;  acc = fmaf(e1, kv1, acc); }
        if (c > 2) { s += e2;  acc = fmaf(e2, kv2, acc); }
        if (c > 3) { s += e3;  acc = fmaf(e3, kv3, acc); }
    }
    g_af[(size_t)n * DD + off] = acc / s;
}

// ---------------- fused pooling head (64 blocks, software grid barrier) ---------
__device__ __forceinline__ void gridBar(int* bar, int expected) {
    __syncthreads();
    if (threadIdx.x == 0) {
        __threadfence();
        atomicAdd(bar, 1);
        while (atomicAdd(bar, 0) < expected) { }
    }
    __syncthreads();
}

__global__ void __launch_bounds__(256) pool_all(const float* __restrict__ F,
        const float* __restrict__ ow, const float* __restrict__ ob,
        float* __restrict__ out) {
    __shared__ float sm[8];
    int b = blockIdx.x, tid = threadIdx.x;
    int n0 = b * 64;
    float v = (tid < 64) ? g_A[n0 + tid] : -1e30f;
    float bm = blockMax256(v, sm);
    if (tid == 0) g_pmax[b] = bm;
    gridBar(&g_bar1, 64);
    float pm = (tid < 64) ? g_pmax[tid] : -1e30f;
    float gmax = blockMax256(pm, sm);
    float acc = 0.f;
    for (int j = 0; j < 64; j++) {
        float w = __expf(g_A[n0 + j] - gmax);
        acc = fmaf(w, F[(size_t)(n0 + j) * DD + tid], acc);
    }
    g_part[(size_t)b * DD + tid] = acc;
    float e = (tid < 64) ? __expf(g_A[n0 + tid] - gmax) : 0.f;
    float ps = blockSum256(e, sm);
    if (tid == 0) { g_psum[b] = ps; __threadfence(); }
    gridBar(&g_bar2, 64);
    if (b == 0) {
        __shared__ float pooled[DD];
        float a = 0.f;
        for (int q = 0; q < 64; q++) a += g_part[(size_t)q * DD + tid];
        float pv = (tid < 64) ? g_psum[tid] : 0.f;
        float tot = blockSum256(pv, sm);
        pooled[tid] = a / tot;
        __syncthreads();
        int h = tid >> 5, lane = tid & 31;
        if (h < 4) {
            const float* w = ow + (size_t)h * DD;
            float o = 0.f;
            for (int k2 = lane; k2 < DD; k2 += 32) o = fmaf(pooled[k2], w[k2], o);
            o = warpSum(o);
            if (lane == 0) out[h] = o + ob[h];
        }
    }
}

// ---------------- host orchestration (stream-forked graph) ----------------
struct DevPtrs {
    float *Xn, *En, *q, *k, *af, *X1, *X2;
};

static DevPtrs s_p = {};
static cudaStream_t s_side = 0;
static cudaEvent_t s_evStart, s_evEg1, s_evQK1, s_evX1, s_evEg2, s_evQK2;
static bool s_init = false;

static void one_time_init() {
    if (s_init) return;
    cudaGetSymbolAddress((void**)&s_p.Xn, g_Xn);
    cudaGetSymbolAddress((void**)&s_p.En, g_En);
    cudaGetSymbolAddress((void**)&s_p.q,  g_q);
    cudaGetSymbolAddress((void**)&s_p.k,  g_k);
    cudaGetSymbolAddress((void**)&s_p.af, g_af);
    cudaGetSymbolAddress((void**)&s_p.X1, g_X1);
    cudaGetSymbolAddress((void**)&s_p.X2, g_X2);
    cudaStreamCreateWithFlags(&s_side, cudaStreamNonBlocking);
    cudaEventCreateWithFlags(&s_evStart, cudaEventDisableTiming);
    cudaEventCreateWithFlags(&s_evEg1,   cudaEventDisableTiming);
    cudaEventCreateWithFlags(&s_evQK1,   cudaEventDisableTiming);
    cudaEventCreateWithFlags(&s_evX1,    cudaEventDisableTiming);
    cudaEventCreateWithFlags(&s_evEg2,   cudaEventDisableTiming);
    cudaEventCreateWithFlags(&s_evQK2,   cudaEventDisableTiming);
    s_init = true;
}

extern "C" void kernel_launch(void* const* d_in, const int* in_sizes, int n_in,
                              void* d_out, int out_size) {
    (void)in_sizes; (void)n_in; (void)out_size;
    const float* X     = (const float*)d_in[0];
    const float* H     = (const float*)d_in[1];
    const float* Wq_w  = (const float*)d_in[2];
    const float* Wq_b  = (const float*)d_in[3];
    const float* Wkn_w = (const float*)d_in[4];
    const float* Wkn_b = (const float*)d_in[5];
    const float* Wkt_w = (const float*)d_in[6];
    const float* Wkt_b = (const float*)d_in[7];
    const float* Wks_w = (const float*)d_in[8];
    const float* Wks_b = (const float*)d_in[9];
    const float* fc_w  = (const float*)d_in[10];
    const float* fc_b  = (const float*)d_in[11];
    const float* ln_g  = (const float*)d_in[12];
    const float* ln_b  = (const float*)d_in[13];
    const float* aw    = (const float*)d_in[14];
    const float* ab    = (const float*)d_in[15];
    const float* bw    = (const float*)d_in[16];
    const float* bb    = (const float*)d_in[17];
    const float* cw    = (const float*)d_in[18];
    const float* out_w = (const float*)d_in[20];
    const float* out_b = (const float*)d_in[21];
    float* out = (float*)d_out;

    one_time_init();
    const DevPtrs& p = s_p;
    const int WOFF = DD * DD;
    dim3 grid(32, 8);   // 128x32 tiles -> 256 blocks -> 2/SM

    // fork side stream off the capture-origin (default) stream
    cudaEventRecord(s_evStart, 0);
    cudaStreamWaitEvent(s_side, s_evStart, 0);

    // ---- main: structure build (single pass: row lists + bucketed CSC) ----
    init_k<<<32, 256>>>();
    build_rows<<<512, 256>>>(H);

    // ---- side: layer-1 q path (needs only X) ----
    ln_rows<<<512, 256, 0, s_side>>>(X, p.Xn, ln_g, ln_b);
    gemm_tc<0><<<grid, 256, 0, s_side>>>(p.Xn, Wq_w, Wq_b, p.q, nullptr);

    // ---- main: layer-1 edge path ----
    egather_all<<<NN + 128, 256>>>(X, ln_g, ln_b);
    cudaEventRecord(s_evEg1, 0);
    gemm_tc<0><<<grid, 256>>>(p.En, Wkn_w, Wkn_b, p.k, nullptr);

    // ---- side: ktail after egather partials ----
    cudaStreamWaitEvent(s_side, s_evEg1, 0);
    ktail_fin<<<32, 256, 0, s_side>>>(Wkt_w, Wkt_b, Wks_w, Wks_b, ln_g, ln_b);
    cudaEventRecord(s_evQK1, s_side);

    // ---- main: join, attention, fc ----
    cudaStreamWaitEvent(0, s_evQK1, 0);
    attn_k<<<NN, 256>>>();
    gemm_tc<1><<<grid, 256>>>(p.af, fc_w, fc_b, p.X1, X);
    cudaEventRecord(s_evX1, 0);

    // ---- side: layer-2 q path ----
    cudaStreamWaitEvent(s_side, s_evX1, 0);
    ln_rows<<<512, 256, 0, s_side>>>(p.X1, p.Xn, ln_g + DD, ln_b + DD);
    gemm_tc<0><<<grid, 256, 0, s_side>>>(p.Xn, Wq_w + WOFF, Wq_b + DD, p.q, nullptr);

    // ---- main: layer-2 edge path ----
    egather_all<<<NN + 128, 256>>>(p.X1, ln_g + DD, ln_b + DD);
    cudaEventRecord(s_evEg2, 0);
    gemm_tc<0><<<grid, 256>>>(p.En, Wkn_w + WOFF, Wkn_b + DD, p.k, nullptr);

    cudaStreamWaitEvent(s_side, s_evEg2, 0);
    ktail_fin<<<32, 256, 0, s_side>>>(Wkt_w + WOFF, Wkt_b + DD,
                                      Wks_w + WOFF, Wks_b + DD,
                                      ln_g + DD, ln_b + DD);
    cudaEventRecord(s_evQK2, s_side);

    cudaStreamWaitEvent(0, s_evQK2, 0);
    attn_k<<<NN, 256>>>();
    gemm_tc<1><<<grid, 256>>>(p.af, fc_w + WOFF, fc_b + DD, p.X2, p.X1);

    // ---- pooling head ----
    gemm_gated<<<dim3(32, 4), 256>>>(p.X2, aw, ab, bw, bb, cw);
    pool_all<<<64, 256>>>(p.X2, out_w, out_b, out);
}

// round 16
// speedup vs baseline: 1.0571x; 1.0302x over previous
#include <cuda_runtime.h>
#include <mma.h>
#include <math.h>
#include <stdint.h>

using namespace nvcuda;

#define NN   4096
#define DD   256
#define MM   4100
#define RCAP 96
#define CCAP 96          // bucket capacity per sparse column
#define TCAP 2560        // bucket capacity per dense tail column
#define TBASE (NN * CCAP)

// ---------------- scratch (device globals) ----------------
__device__ __align__(16) float g_deg[MM];
__device__ int   g_row_cnt[NN];
__device__ int   g_row_idx[NN * RCAP];
__device__ __align__(16) float g_row_val[NN * RCAP];
__device__ int   g_col_fill[MM];
__device__ int   g_col_idx[NN * CCAP + 4 * TCAP];
__device__ __align__(16) float g_col_val[NN * CCAP + 4 * TCAP];

__device__ __align__(16) float g_Xn[NN * DD];
__device__ __align__(16) float g_En[NN * DD];
__device__ __align__(16) float g_q [NN * DD];
__device__ __align__(16) float g_k [MM * DD];
__device__ __align__(16) float g_af[NN * DD];
__device__ __align__(16) float g_X1[NN * DD];
__device__ __align__(16) float g_X2[NN * DD];
__device__ __align__(16) float g_A [NN];
__device__ __align__(16) float g_part[64 * DD];
__device__ __align__(16) float g_epart[4 * 32 * DD];
__device__ float g_pmax[64];
__device__ float g_psum[64];
__device__ int   g_bar1;
__device__ int   g_bar2;

// ---------------- helpers ----------------
__device__ __forceinline__ float warpSum(float v) {
#pragma unroll
    for (int o = 16; o; o >>= 1) v += __shfl_xor_sync(0xffffffffu, v, o);
    return v;
}
__device__ __forceinline__ float warpMax(float v) {
#pragma unroll
    for (int o = 16; o; o >>= 1) v = fmaxf(v, __shfl_xor_sync(0xffffffffu, v, o));
    return v;
}
__device__ __forceinline__ float blockSum256(float v, float* sm) {
    int lane = threadIdx.x & 31, w = threadIdx.x >> 5;
    v = warpSum(v);
    if (lane == 0) sm[w] = v;
    __syncthreads();
    if (threadIdx.x == 0) {
        float s = 0.f;
#pragma unroll
        for (int i = 0; i < 8; i++) s += sm[i];
        sm[0] = s;
    }
    __syncthreads();
    float r = sm[0];
    __syncthreads();
    return r;
}
__device__ __forceinline__ float blockMax256(float v, float* sm) {
    int lane = threadIdx.x & 31, w = threadIdx.x >> 5;
    v = warpMax(v);
    if (lane == 0) sm[w] = v;
    __syncthreads();
    if (threadIdx.x == 0) {
        float s = sm[0];
#pragma unroll
        for (int i = 1; i < 8; i++) s = fmaxf(s, sm[i]);
        sm[0] = s;
    }
    __syncthreads();
    float r = sm[0];
    __syncthreads();
    return r;
}

__device__ __forceinline__ int bucketBase(int m) {
    return (m < NN) ? m * CCAP : TBASE + (m - NN) * TCAP;
}
__device__ __forceinline__ int bucketCap(int m) {
    return (m < NN) ? CCAP : TCAP;
}

// ---------------- structure build ----------------
__global__ void init_k() {
    int i = blockIdx.x * blockDim.x + threadIdx.x;
    int st = gridDim.x * blockDim.x;
    for (int j = i; j < MM; j += st) { g_col_fill[j] = 0; g_deg[j] = 0.f; }
    for (int j = i; j < NN; j += st) g_A[j] = 0.f;
    if (i == 0) { g_bar1 = 0; g_bar2 = 0; }
}

// warp per row; MLP=4 loads. Builds ordered row lists AND scatters nonzeros
// directly into the bucketed CSC (slot = atomicAdd on fill) in ONE pass over H.
__device__ __forceinline__ void scatterNZ(int m, int warp, float v,
                                          int* ri, float* rv, int pos) {
    ri[pos] = m; rv[pos] = v;
    atomicAdd(&g_deg[m], v);
    int p = atomicAdd(&g_col_fill[m], 1);
    if (p < bucketCap(m)) {
        int o = bucketBase(m) + p;
        g_col_idx[o] = warp;
        g_col_val[o] = v;
    }
}

__global__ void __launch_bounds__(256) build_rows(const float* __restrict__ H) {
    int warp = (blockIdx.x * blockDim.x + threadIdx.x) >> 5;
    if (warp >= NN) return;
    int lane = threadIdx.x & 31;
    const float4* row4 = (const float4*)(H + (size_t)warp * MM);  // 1025 float4
    int* ri = g_row_idx + (size_t)warp * RCAP;
    float* rv = g_row_val + (size_t)warp * RCAP;
    int base = 0;
#pragma unroll 1
    for (int it = 0; it < 8; it++) {
        float4 v[4];
#pragma unroll
        for (int sub = 0; sub < 4; sub++)
            v[sub] = row4[it * 128 + sub * 32 + lane];
#pragma unroll
        for (int sub = 0; sub < 4; sub++) {
            int colbase = (it * 128 + sub * 32 + lane) * 4;
            int c0 = v[sub].x != 0.f, c1 = v[sub].y != 0.f;
            int c2 = v[sub].z != 0.f, c3 = v[sub].w != 0.f;
            int cnt = c0 + c1 + c2 + c3;
            int inc = cnt;
#pragma unroll
            for (int o = 1; o < 32; o <<= 1) {
                int t = __shfl_up_sync(0xffffffffu, inc, o);
                if (lane >= o) inc += t;
            }
            int tot = __shfl_sync(0xffffffffu, inc, 31);
            int pos = base + inc - cnt;
            if (c0) { scatterNZ(colbase,     warp, v[sub].x, ri, rv, pos); pos++; }
            if (c1) { scatterNZ(colbase + 1, warp, v[sub].y, ri, rv, pos); pos++; }
            if (c2) { scatterNZ(colbase + 2, warp, v[sub].z, ri, rv, pos); pos++; }
            if (c3) { scatterNZ(colbase + 3, warp, v[sub].w, ri, rv, pos); pos++; }
            base += tot;
        }
    }
    // tail: float4 #1024 covers cols 4096..4099 (lane 0 only)
    {
        float4 v = (lane == 0) ? row4[1024] : make_float4(0.f, 0.f, 0.f, 0.f);
        int colbase = 4096;
        int c0 = (lane == 0) && (v.x != 0.f), c1 = (lane == 0) && (v.y != 0.f);
        int c2 = (lane == 0) && (v.z != 0.f), c3 = (lane == 0) && (v.w != 0.f);
        int cnt = c0 + c1 + c2 + c3;
        int inc = cnt;
#pragma unroll
        for (int o = 1; o < 32; o <<= 1) {
            int t = __shfl_up_sync(0xffffffffu, inc, o);
            if (lane >= o) inc += t;
        }
        int tot = __shfl_sync(0xffffffffu, inc, 31);
        int pos = base + inc - cnt;
        if (c0) { scatterNZ(colbase,     warp, v.x, ri, rv, pos); pos++; }
        if (c1) { scatterNZ(colbase + 1, warp, v.y, ri, rv, pos); pos++; }
        if (c2) { scatterNZ(colbase + 2, warp, v.z, ri, rv, pos); pos++; }
        if (c3) { scatterNZ(colbase + 3, warp, v.w, ri, rv, pos); pos++; }
        base += tot;
    }
    if (lane == 0) g_row_cnt[warp] = base;
}

// ---------------- per-layer kernels ----------------
__global__ void ln_rows(const float* __restrict__ X, float* __restrict__ O,
                        const float* __restrict__ g, const float* __restrict__ b) {
    int warp = (blockIdx.x * blockDim.x + threadIdx.x) >> 5;
    if (warp >= NN) return;
    int lane = threadIdx.x & 31;
    const float4* x4 = (const float4*)(X + (size_t)warp * DD);
    float4 v0 = x4[lane], v1 = x4[lane + 32];
    float s = v0.x + v0.y + v0.z + v0.w + v1.x + v1.y + v1.z + v1.w;
    s = warpSum(s);
    float mean = s * (1.f / 256.f);
    float c0x = v0.x - mean, c0y = v0.y - mean, c0z = v0.z - mean, c0w = v0.w - mean;
    float c1x = v1.x - mean, c1y = v1.y - mean, c1z = v1.z - mean, c1w = v1.w - mean;
    float ss = c0x*c0x + c0y*c0y + c0z*c0z + c0w*c0w + c1x*c1x + c1y*c1y + c1z*c1z + c1w*c1w;
    ss = warpSum(ss);
    float rs = rsqrtf(ss * (1.f / 256.f) + 1e-5f);
    const float4* g4 = (const float4*)g;
    const float4* b4 = (const float4*)b;
    float4 G0 = g4[lane], G1 = g4[lane + 32], B0 = b4[lane], B1 = b4[lane + 32];
    float4* o4 = (float4*)(O + (size_t)warp * DD);
    o4[lane]      = make_float4(c0x*rs*G0.x + B0.x, c0y*rs*G0.y + B0.y,
                                c0z*rs*G0.z + B0.z, c0w*rs*G0.w + B0.w);
    o4[lane + 32] = make_float4(c1x*rs*G1.x + B1.x, c1y*rs*G1.y + B1.y,
                                c1z*rs*G1.z + B1.z, c1w*rs*G1.w + B1.w);
}

// blocks [0,128): dense tail partials (long poles -> scheduled FIRST)
// blocks [128,NN+128): sparse edge gather + LN -> g_En  (bucketed CSC)
__global__ void __launch_bounds__(256) egather_all(const float* __restrict__ X,
        const float* __restrict__ g, const float* __restrict__ b) {
    __shared__ int sidx[CCAP];
    __shared__ float sval[CCAP];
    __shared__ float sm[8];
    int bid = blockIdx.x, d = threadIdx.x;
    if (bid >= 128) {
        int m = bid - 128;
        int p0 = m * CCAP;
        int cnt = min(g_col_fill[m], CCAP);
        if (d < cnt) { sidx[d] = g_col_idx[p0 + d]; sval[d] = g_col_val[p0 + d]; }
        __syncthreads();
        float a0 = 0.f, a1 = 0.f, a2 = 0.f, a3 = 0.f;
        int j = 0;
        for (; j + 4 <= cnt; j += 4) {
            int n0 = sidx[j], n1 = sidx[j+1], n2 = sidx[j+2], n3 = sidx[j+3];
            float x0 = X[(size_t)n0 * DD + d], x1 = X[(size_t)n1 * DD + d];
            float x2 = X[(size_t)n2 * DD + d], x3 = X[(size_t)n3 * DD + d];
            a0 = fmaf(sval[j],   x0, a0); a1 = fmaf(sval[j+1], x1, a1);
            a2 = fmaf(sval[j+2], x2, a2); a3 = fmaf(sval[j+3], x3, a3);
        }
        for (; j < cnt; j++) a0 = fmaf(sval[j], X[(size_t)sidx[j] * DD + d], a0);
        float acc = ((a0 + a1) + (a2 + a3)) / g_deg[m];
        float mean = blockSum256(acc, sm) * (1.f / 256.f);
        float c = acc - mean;
        float var = blockSum256(c * c, sm) * (1.f / 256.f);
        float rs = rsqrtf(var + 1e-5f);
        g_En[(size_t)m * DD + d] = c * rs * g[d] + b[d];
    } else {
        int t = bid;
        int e = t >> 5, slice = t & 31;
        int m = NN + e;
        int p0 = TBASE + e * TCAP;
        int cnt = min(g_col_fill[m], TCAP);
        int per = (cnt + 31) / 32;
        int s0 = p0 + slice * per;
        int s1 = min(s0 + per, p0 + cnt);
        float a0 = 0.f, a1 = 0.f, a2 = 0.f, a3 = 0.f;
        int p = s0;
        for (; p + 4 <= s1; p += 4) {
            int n0 = g_col_idx[p], n1 = g_col_idx[p+1], n2 = g_col_idx[p+2], n3 = g_col_idx[p+3];
            float w0 = g_col_val[p], w1 = g_col_val[p+1], w2 = g_col_val[p+2], w3 = g_col_val[p+3];
            a0 = fmaf(w0, X[(size_t)n0 * DD + d], a0);
            a1 = fmaf(w1, X[(size_t)n1 * DD + d], a1);
            a2 = fmaf(w2, X[(size_t)n2 * DD + d], a2);
            a3 = fmaf(w3, X[(size_t)n3 * DD + d], a3);
        }
        for (; p < s1; p++) a0 = fmaf(g_col_val[p], X[(size_t)g_col_idx[p] * DD + d], a0);
        g_epart[(size_t)(e * 32 + slice) * DD + d] = (a0 + a1) + (a2 + a3);
    }
}

// 32 blocks: each redundantly reduces dense-tail partials + LN in smem, then
// computes its share of the tail k projections.
__global__ void __launch_bounds__(256) ktail_fin(
        const float* __restrict__ Wkt, const float* __restrict__ bkt,
        const float* __restrict__ Wks, const float* __restrict__ bks,
        const float* __restrict__ g, const float* __restrict__ b) {
    __shared__ __align__(16) float e[4][DD];
    __shared__ float smr[8];
    int tid = threadIdx.x;
#pragma unroll
    for (int r = 0; r < 4; r++) {
        float acc = 0.f;
#pragma unroll
        for (int s = 0; s < 32; s++) acc += g_epart[(size_t)(r * 32 + s) * DD + tid];
        acc /= g_deg[NN + r];
        float mean = blockSum256(acc, smr) * (1.f / 256.f);
        float c = acc - mean;
        float var = blockSum256(c * c, smr) * (1.f / 256.f);
        float rs = rsqrtf(var + 1e-5f);
        e[r][tid] = c * rs * g[tid] + b[tid];
    }
    __syncthreads();
    int w = tid >> 5, lane = tid & 31;
    int gw = blockIdx.x * 8 + w;   // 0..255
    for (int t = gw; t < 4 * DD; t += 256) {
        int r = t >> 8, o = t & 255;
        const float* wrow = ((r < 3) ? Wkt : Wks) + (size_t)o * DD;
        const float4* w4 = (const float4*)wrow;
        const float4* e4 = (const float4*)e[r];
        float4 a = w4[lane], bb = e4[lane];
        float acc = a.x*bb.x + a.y*bb.y + a.z*bb.z + a.w*bb.w;
        float4 a2 = w4[lane + 32], b2 = e4[lane + 32];
        acc += a2.x*b2.x + a2.y*b2.y + a2.z*b2.z + a2.w*b2.w;
        acc = warpSum(acc);
        if (lane == 0) g_k[(size_t)(NN + r) * DD + o] = acc + ((r < 3) ? bkt[o] : bks[o]);
    }
}

// ---------------- tf32 tensor-core GEMM (128x32 tile, 256 blocks, 2/SM) ----------
// ASTRIDE 36 (mod 32 = 4): halves the smem bank conflicts on wmma fragment
// column walks vs 40 (mod 32 = 8); float4 staging stays 16B-aligned.
#define ASTRIDE 36
#define CSTRIDE 68
#define CST2 36
template <int EPI>
__global__ void __launch_bounds__(256) gemm_tc(const float* __restrict__ A,
        const float* __restrict__ W, const float* __restrict__ bias,
        float* __restrict__ C, const float* __restrict__ R) {
    __shared__ __align__(16) float sm[160 * ASTRIDE];
    float* As = sm;                    // 128 x ASTRIDE
    float* Ws = sm + 128 * ASTRIDE;    // 32 x ASTRIDE
    int tid = threadIdx.x;
    int wid = tid >> 5;
    int wr = wid >> 1;      // 0..3 -> rows 32*wr
    int wc = wid & 1;       // 0..1 -> cols 16*wc
    int rowBase = blockIdx.x * 128;
    int colBase = blockIdx.y * 32;

    wmma::fragment<wmma::accumulator, 16, 16, 8, float> acc[2];
    wmma::fill_fragment(acc[0], 0.f);
    wmma::fill_fragment(acc[1], 0.f);

#pragma unroll 1
    for (int k0 = 0; k0 < 256; k0 += 32) {
#pragma unroll
        for (int i = 0; i < 4; i++) {
            int idx = tid + i * 256;
            int row = idx >> 3;
            int c4 = (idx & 7) * 4;
            float4 v = *(const float4*)(A + (size_t)(rowBase + row) * DD + k0 + c4);
            *(float4*)&As[row * ASTRIDE + c4] = v;
        }
        {
            int row = tid >> 3;
            int c4 = (tid & 7) * 4;
            float4 v = *(const float4*)(W + (size_t)(colBase + row) * DD + k0 + c4);
            *(float4*)&Ws[row * ASTRIDE + c4] = v;
        }
        __syncthreads();
#pragma unroll
        for (int kk = 0; kk < 32; kk += 8) {
            wmma::fragment<wmma::matrix_a, 16, 16, 8, wmma::precision::tf32, wmma::row_major> a[2];
            wmma::fragment<wmma::matrix_b, 16, 16, 8, wmma::precision::tf32, wmma::col_major> b;
            wmma::load_matrix_sync(a[0], &As[(wr * 32) * ASTRIDE + kk], ASTRIDE);
            wmma::load_matrix_sync(a[1], &As[(wr * 32 + 16) * ASTRIDE + kk], ASTRIDE);
            wmma::load_matrix_sync(b, &Ws[(wc * 16) * ASTRIDE + kk], ASTRIDE);
#pragma unroll
            for (int t = 0; t < a[0].num_elements; t++) {
                a[0].x[t] = wmma::__float_to_tf32(a[0].x[t]);
                a[1].x[t] = wmma::__float_to_tf32(a[1].x[t]);
            }
#pragma unroll
            for (int t = 0; t < b.num_elements; t++)
                b.x[t] = wmma::__float_to_tf32(b.x[t]);
            wmma::mma_sync(acc[0], a[0], b, acc[0]);
            wmma::mma_sync(acc[1], a[1], b, acc[1]);
        }
        __syncthreads();
    }
    wmma::store_matrix_sync(&sm[(wr * 32) * CST2 + wc * 16],      acc[0], CST2, wmma::mem_row_major);
    wmma::store_matrix_sync(&sm[(wr * 32 + 16) * CST2 + wc * 16], acc[1], CST2, wmma::mem_row_major);
    __syncthreads();

#pragma unroll
    for (int e4 = 0; e4 < 4; e4++) {
        int linear = tid + e4 * 256;      // 0..1023 float4 slots
        int row = linear >> 3;            // 8 float4 per 32-wide row
        int col = (linear & 7) * 4;
        float4 v = *(float4*)&sm[row * CST2 + col];
        float4 bv = *(const float4*)(bias + colBase + col);
        v.x += bv.x; v.y += bv.y; v.z += bv.z; v.w += bv.w;
        int grow = rowBase + row;
        if (EPI == 1) {
            float4 rv = *(const float4*)(R + (size_t)grow * DD + colBase + col);
            v.x = fmaxf(v.x, 0.f) * 0.5f + 0.5f * rv.x;
            v.y = fmaxf(v.y, 0.f) * 0.5f + 0.5f * rv.y;
            v.z = fmaxf(v.z, 0.f) * 0.5f + 0.5f * rv.z;
            v.w = fmaxf(v.w, 0.f) * 0.5f + 0.5f * rv.w;
        }
        *(float4*)(C + (size_t)grow * DD + colBase + col) = v;
    }
}

// Fused gated-attention GEMM: tanh & sigmoid branches for a 128x64 tile,
// reduced through cw directly into g_A via atomics.
__global__ void __launch_bounds__(256) gemm_gated(const float* __restrict__ A,
        const float* __restrict__ Wa, const float* __restrict__ ba,
        const float* __restrict__ Wb, const float* __restrict__ bb_,
        const float* __restrict__ cw) {
    __shared__ __align__(16) float sm[10240];
    float* As  = sm;           // 128 x ASTRIDE (4608)
    float* Was = sm + 5120;    // 64 x ASTRIDE (2304)
    float* Wbs = sm + 7680;    // 64 x ASTRIDE (2304)
    int tid = threadIdx.x;
    int wid = tid >> 5;
    int wr = wid >> 1;
    int wc = wid & 1;
    int rowBase = blockIdx.x * 128;
    int colBase = blockIdx.y * 64;

    wmma::fragment<wmma::accumulator, 16, 16, 8, float> accA[2][2], accB[2][2];
#pragma unroll
    for (int i = 0; i < 2; i++)
#pragma unroll
        for (int j = 0; j < 2; j++) {
            wmma::fill_fragment(accA[i][j], 0.f);
            wmma::fill_fragment(accB[i][j], 0.f);
        }

#pragma unroll 1
    for (int k0 = 0; k0 < 256; k0 += 32) {
#pragma unroll
        for (int i = 0; i < 4; i++) {
            int idx = tid + i * 256;
            int row = idx >> 3;
            int c4 = (idx & 7) * 4;
            float4 v = *(const float4*)(A + (size_t)(rowBase + row) * DD + k0 + c4);
            *(float4*)&As[row * ASTRIDE + c4] = v;
        }
#pragma unroll
        for (int i = 0; i < 2; i++) {
            int idx = tid + i * 256;
            int row = idx >> 3;
            int c4 = (idx & 7) * 4;
            float4 va = *(const float4*)(Wa + (size_t)(colBase + row) * DD + k0 + c4);
            float4 vb = *(const float4*)(Wb + (size_t)(colBase + row) * DD + k0 + c4);
            *(float4*)&Was[row * ASTRIDE + c4] = va;
            *(float4*)&Wbs[row * ASTRIDE + c4] = vb;
        }
        __syncthreads();
#pragma unroll
        for (int kk = 0; kk < 32; kk += 8) {
            wmma::fragment<wmma::matrix_a, 16, 16, 8, wmma::precision::tf32, wmma::row_major> a[2];
            wmma::fragment<wmma::matrix_b, 16, 16, 8, wmma::precision::tf32, wmma::col_major> bA[2], bB[2];
            wmma::load_matrix_sync(a[0], &As[(wr * 32) * ASTRIDE + kk], ASTRIDE);
            wmma::load_matrix_sync(a[1], &As[(wr * 32 + 16) * ASTRIDE + kk], ASTRIDE);
            wmma::load_matrix_sync(bA[0], &Was[(wc * 32) * ASTRIDE + kk], ASTRIDE);
            wmma::load_matrix_sync(bA[1], &Was[(wc * 32 + 16) * ASTRIDE + kk], ASTRIDE);
            wmma::load_matrix_sync(bB[0], &Wbs[(wc * 32) * ASTRIDE + kk], ASTRIDE);
            wmma::load_matrix_sync(bB[1], &Wbs[(wc * 32 + 16) * ASTRIDE + kk], ASTRIDE);
#pragma unroll
            for (int t = 0; t < a[0].num_elements; t++) {
                a[0].x[t] = wmma::__float_to_tf32(a[0].x[t]);
                a[1].x[t] = wmma::__float_to_tf32(a[1].x[t]);
            }
#pragma unroll
            for (int t = 0; t < bA[0].num_elements; t++) {
                bA[0].x[t] = wmma::__float_to_tf32(bA[0].x[t]);
                bA[1].x[t] = wmma::__float_to_tf32(bA[1].x[t]);
                bB[0].x[t] = wmma::__float_to_tf32(bB[0].x[t]);
                bB[1].x[t] = wmma::__float_to_tf32(bB[1].x[t]);
            }
#pragma unroll
            for (int i = 0; i < 2; i++)
#pragma unroll
                for (int j = 0; j < 2; j++) {
                    wmma::mma_sync(accA[i][j], a[i], bA[j], accA[i][j]);
                    wmma::mma_sync(accB[i][j], a[i], bB[j], accB[i][j]);
                }
        }
        __syncthreads();
    }
#pragma unroll
    for (int i = 0; i < 2; i++)
#pragma unroll
        for (int j = 0; j < 2; j++)
            wmma::store_matrix_sync(&sm[(wr * 32 + i * 16) * CSTRIDE + wc * 32 + j * 16],
                                    accA[i][j], CSTRIDE, wmma::mem_row_major);
    __syncthreads();
    float av[8][4];
#pragma unroll
    for (int e4 = 0; e4 < 8; e4++) {
        int linear = tid + e4 * 256;
        int row = linear >> 4;
        int col = (linear & 15) * 4;
        float4 v = *(float4*)&sm[row * CSTRIDE + col];
        float4 bv = *(const float4*)(ba + colBase + col);
        av[e4][0] = tanhf(v.x + bv.x); av[e4][1] = tanhf(v.y + bv.y);
        av[e4][2] = tanhf(v.z + bv.z); av[e4][3] = tanhf(v.w + bv.w);
    }
    __syncthreads();
#pragma unroll
    for (int i = 0; i < 2; i++)
#pragma unroll
        for (int j = 0; j < 2; j++)
            wmma::store_matrix_sync(&sm[(wr * 32 + i * 16) * CSTRIDE + wc * 32 + j * 16],
                                    accB[i][j], CSTRIDE, wmma::mem_row_major);
    __syncthreads();
#pragma unroll
    for (int e4 = 0; e4 < 8; e4++) {
        int linear = tid + e4 * 256;
        int row = linear >> 4;
        int col = (linear & 15) * 4;
        float4 v = *(float4*)&sm[row * CSTRIDE + col];
        float4 bv = *(const float4*)(bb_ + colBase + col);
        float4 cv = *(const float4*)(cw + colBase + col);
        float s0 = 1.f / (1.f + __expf(-(v.x + bv.x)));
        float s1 = 1.f / (1.f + __expf(-(v.y + bv.y)));
        float s2 = 1.f / (1.f + __expf(-(v.z + bv.z)));
        float s3 = 1.f / (1.f + __expf(-(v.w + bv.w)));
        float partial = av[e4][0]*s0*cv.x + av[e4][1]*s1*cv.y
                      + av[e4][2]*s2*cv.z + av[e4][3]*s3*cv.w;
#pragma unroll
        for (int o = 8; o; o >>= 1)
            partial += __shfl_down_sync(0xffffffffu, partial, o, 16);
        if ((tid & 15) == 0) atomicAdd(&g_A[rowBase + row], partial);
    }
}

// sparse masked MHA; block per node, warp per head. Plain softmax (bounded scores).
__global__ void __launch_bounds__(256) attn_k() {
    int n = blockIdx.x;
    int tid = threadIdx.x;
    int h = tid >> 5, lane = tid & 31;
    __shared__ int sidx[RCAP];
    int cnt = g_row_cnt[n];
    if (tid < cnt) sidx[tid] = g_row_idx[(size_t)n * RCAP + tid];
    __syncthreads();
    int off = h * 32 + lane;
    float qv = g_q[(size_t)n * DD + off];
    float s = 0.f, acc = 0.f;
    const float sc = 0.17677669529663687f;  // 1/sqrt(32)
    for (int j0 = 0; j0 < cnt; j0 += 4) {
        int c = cnt - j0;
        float kv0 = g_k[(size_t)sidx[j0] * DD + off];
        float kv1 = (c > 1) ? g_k[(size_t)sidx[j0+1] * DD + off] : 0.f;
        float kv2 = (c > 2) ? g_k[(size_t)sidx[j0+2] * DD + off] : 0.f;
        float kv3 = (c > 3) ? g_k[(size_t)sidx[j0+3] * DD + off] : 0.f;
        float p0 = qv * kv0, p1 = qv * kv1, p2 = qv * kv2, p3 = qv * kv3;
#pragma unroll
        for (int o = 16; o; o >>= 1) {
            p0 += __shfl_xor_sync(0xffffffffu, p0, o);
            p1 += __shfl_xor_sync(0xffffffffu, p1, o);
            p2 += __shfl_xor_sync(0xffffffffu, p2, o);
            p3 += __shfl_xor_sync(0xffffffffu, p3, o);
        }
        float e0 = __expf(p0 * sc);
        float e1 = __expf(p1 * sc);
        float e2 = __expf(p2 * sc);
        float e3 = __expf(p3 * sc);
        s += e0;               acc = fmaf(e0, kv0, acc);
        if (c > 1) { s += e1;  acc = fmaf(e1, kv1, acc); }
        if (c > 2) { s += e2;  acc = fmaf(e2, kv2, acc); }
        if (c > 3) { s += e3;  acc = fmaf(e3, kv3, acc); }
    }
    g_af[(size_t)n * DD + off] = acc / s;
}

// ---------------- fused pooling head (64 blocks, software grid barrier) ---------
__device__ __forceinline__ void gridBar(int* bar, int expected) {
    __syncthreads();
    if (threadIdx.x == 0) {
        __threadfence();
        atomicAdd(bar, 1);
        while (atomicAdd(bar, 0) < expected) { }
    }
    __syncthreads();
}

__global__ void __launch_bounds__(256) pool_all(const float* __restrict__ F,
        const float* __restrict__ ow, const float* __restrict__ ob,
        float* __restrict__ out) {
    __shared__ float sm[8];
    int b = blockIdx.x, tid = threadIdx.x;
    int n0 = b * 64;
    float v = (tid < 64) ? g_A[n0 + tid] : -1e30f;
    float bm = blockMax256(v, sm);
    if (tid == 0) g_pmax[b] = bm;
    gridBar(&g_bar1, 64);
    float pm = (tid < 64) ? g_pmax[tid] : -1e30f;
    float gmax = blockMax256(pm, sm);
    float acc = 0.f;
    for (int j = 0; j < 64; j++) {
        float w = __expf(g_A[n0 + j] - gmax);
        acc = fmaf(w, F[(size_t)(n0 + j) * DD + tid], acc);
    }
    g_part[(size_t)b * DD + tid] = acc;
    float e = (tid < 64) ? __expf(g_A[n0 + tid] - gmax) : 0.f;
    float ps = blockSum256(e, sm);
    if (tid == 0) { g_psum[b] = ps; __threadfence(); }
    gridBar(&g_bar2, 64);
    if (b == 0) {
        __shared__ float pooled[DD];
        float a = 0.f;
        for (int q = 0; q < 64; q++) a += g_part[(size_t)q * DD + tid];
        float pv = (tid < 64) ? g_psum[tid] : 0.f;
        float tot = blockSum256(pv, sm);
        pooled[tid] = a / tot;
        __syncthreads();
        int h = tid >> 5, lane = tid & 31;
        if (h < 4) {
            const float* w = ow + (size_t)h * DD;
            float o = 0.f;
            for (int k2 = lane; k2 < DD; k2 += 32) o = fmaf(pooled[k2], w[k2], o);
            o = warpSum(o);
            if (lane == 0) out[h] = o + ob[h];
        }
    }
}

// ---------------- host orchestration (stream-forked graph) ----------------
struct DevPtrs {
    float *Xn, *En, *q, *k, *af, *X1, *X2;
};

static DevPtrs s_p = {};
static cudaStream_t s_side = 0;
static cudaEvent_t s_evStart, s_evEg1, s_evQK1, s_evX1, s_evEg2, s_evQK2;
static bool s_init = false;

static void one_time_init() {
    if (s_init) return;
    cudaGetSymbolAddress((void**)&s_p.Xn, g_Xn);
    cudaGetSymbolAddress((void**)&s_p.En, g_En);
    cudaGetSymbolAddress((void**)&s_p.q,  g_q);
    cudaGetSymbolAddress((void**)&s_p.k,  g_k);
    cudaGetSymbolAddress((void**)&s_p.af, g_af);
    cudaGetSymbolAddress((void**)&s_p.X1, g_X1);
    cudaGetSymbolAddress((void**)&s_p.X2, g_X2);
    cudaStreamCreateWithFlags(&s_side, cudaStreamNonBlocking);
    cudaEventCreateWithFlags(&s_evStart, cudaEventDisableTiming);
    cudaEventCreateWithFlags(&s_evEg1,   cudaEventDisableTiming);
    cudaEventCreateWithFlags(&s_evQK1,   cudaEventDisableTiming);
    cudaEventCreateWithFlags(&s_evX1,    cudaEventDisableTiming);
    cudaEventCreateWithFlags(&s_evEg2,   cudaEventDisableTiming);
    cudaEventCreateWithFlags(&s_evQK2,   cudaEventDisableTiming);
    s_init = true;
}

extern "C" void kernel_launch(void* const* d_in, const int* in_sizes, int n_in,
                              void* d_out, int out_size) {
    (void)in_sizes; (void)n_in; (void)out_size;
    const float* X     = (const float*)d_in[0];
    const float* H     = (const float*)d_in[1];
    const float* Wq_w  = (const float*)d_in[2];
    const float* Wq_b  = (const float*)d_in[3];
    const float* Wkn_w = (const float*)d_in[4];
    const float* Wkn_b = (const float*)d_in[5];
    const float* Wkt_w = (const float*)d_in[6];
    const float* Wkt_b = (const float*)d_in[7];
    const float* Wks_w = (const float*)d_in[8];
    const float* Wks_b = (const float*)d_in[9];
    const float* fc_w  = (const float*)d_in[10];
    const float* fc_b  = (const float*)d_in[11];
    const float* ln_g  = (const float*)d_in[12];
    const float* ln_b  = (const float*)d_in[13];
    const float* aw    = (const float*)d_in[14];
    const float* ab    = (const float*)d_in[15];
    const float* bw    = (const float*)d_in[16];
    const float* bb    = (const float*)d_in[17];
    const float* cw    = (const float*)d_in[18];
    const float* out_w = (const float*)d_in[20];
    const float* out_b = (const float*)d_in[21];
    float* out = (float*)d_out;

    one_time_init();
    const DevPtrs& p = s_p;
    const int WOFF = DD * DD;
    dim3 grid(32, 8);   // 128x32 tiles -> 256 blocks -> 2/SM

    // fork side stream off the capture-origin (default) stream
    cudaEventRecord(s_evStart, 0);
    cudaStreamWaitEvent(s_side, s_evStart, 0);

    // ---- main: structure build (single pass: row lists + bucketed CSC) ----
    init_k<<<32, 256>>>();
    build_rows<<<512, 256>>>(H);

    // ---- side: layer-1 q path (needs only X) ----
    ln_rows<<<512, 256, 0, s_side>>>(X, p.Xn, ln_g, ln_b);
    gemm_tc<0><<<grid, 256, 0, s_side>>>(p.Xn, Wq_w, Wq_b, p.q, nullptr);

    // ---- main: layer-1 edge path ----
    egather_all<<<NN + 128, 256>>>(X, ln_g, ln_b);
    cudaEventRecord(s_evEg1, 0);
    gemm_tc<0><<<grid, 256>>>(p.En, Wkn_w, Wkn_b, p.k, nullptr);

    // ---- side: ktail after egather partials ----
    cudaStreamWaitEvent(s_side, s_evEg1, 0);
    ktail_fin<<<32, 256, 0, s_side>>>(Wkt_w, Wkt_b, Wks_w, Wks_b, ln_g, ln_b);
    cudaEventRecord(s_evQK1, s_side);

    // ---- main: join, attention, fc ----
    cudaStreamWaitEvent(0, s_evQK1, 0);
    attn_k<<<NN, 256>>>();
    gemm_tc<1><<<grid, 256>>>(p.af, fc_w, fc_b, p.X1, X);
    cudaEventRecord(s_evX1, 0);

    // ---- side: layer-2 q path ----
    cudaStreamWaitEvent(s_side, s_evX1, 0);
    ln_rows<<<512, 256, 0, s_side>>>(p.X1, p.Xn, ln_g + DD, ln_b + DD);
    gemm_tc<0><<<grid, 256, 0, s_side>>>(p.Xn, Wq_w + WOFF, Wq_b + DD, p.q, nullptr);

    // ---- main: layer-2 edge path ----
    egather_all<<<NN + 128, 256>>>(p.X1, ln_g + DD, ln_b + DD);
    cudaEventRecord(s_evEg2, 0);
    gemm_tc<0><<<grid, 256>>>(p.En, Wkn_w + WOFF, Wkn_b + DD, p.k, nullptr);

    cudaStreamWaitEvent(s_side, s_evEg2, 0);
    ktail_fin<<<32, 256, 0, s_side>>>(Wkt_w + WOFF, Wkt_b + DD,
                                      Wks_w + WOFF, Wks_b + DD,
                                      ln_g + DD, ln_b + DD);
    cudaEventRecord(s_evQK2, s_side);

    cudaStreamWaitEvent(0, s_evQK2, 0);
    attn_k<<<NN, 256>>>();
    gemm_tc<1><<<grid, 256>>>(p.af, fc_w + WOFF, fc_b + DD, p.X2, p.X1);

    // ---- pooling head ----
    gemm_gated<<<dim3(32, 4), 256>>>(p.X2, aw, ab, bw, bb, cw);
    pool_all<<<64, 256>>>(p.X2, out_w, out_b, out);
}

// round 17
// speedup vs baseline: 1.0757x; 1.0176x over previous
#include <cuda_runtime.h>
#include <mma.h>
#include <math.h>
#include <stdint.h>

using namespace nvcuda;

#define NN   4096
#define DD   256
#define MM   4100
#define RCAP 96
#define CCAP 96          // bucket capacity per sparse column
#define TCAP 2560        // bucket capacity per dense tail column
#define TBASE (NN * CCAP)

// ---------------- scratch (device globals) ----------------
__device__ __align__(16) float g_deg[MM];
__device__ int   g_row_cnt[NN];
__device__ int   g_row_idx[NN * RCAP];
__device__ __align__(16) float g_row_val[NN * RCAP];
__device__ int   g_col_fill[MM];
__device__ int   g_col_idx[NN * CCAP + 4 * TCAP];
__device__ __align__(16) float g_col_val[NN * CCAP + 4 * TCAP];

__device__ __align__(16) float g_Xn[NN * DD];
__device__ __align__(16) float g_En[NN * DD];
__device__ __align__(16) float g_q [NN * DD];
__device__ __align__(16) float g_k [MM * DD];
__device__ __align__(16) float g_af[NN * DD];
__device__ __align__(16) float g_X1[NN * DD];
__device__ __align__(16) float g_X2[NN * DD];
__device__ __align__(16) float g_A [NN];
__device__ __align__(16) float g_part[64 * DD];
__device__ __align__(16) float g_epart[4 * 32 * DD];
__device__ float g_pmax[64];
__device__ float g_psum[64];
__device__ int   g_bar1;
__device__ int   g_bar2;

// ---------------- helpers ----------------
__device__ __forceinline__ float warpSum(float v) {
#pragma unroll
    for (int o = 16; o; o >>= 1) v += __shfl_xor_sync(0xffffffffu, v, o);
    return v;
}
__device__ __forceinline__ float warpMax(float v) {
#pragma unroll
    for (int o = 16; o; o >>= 1) v = fmaxf(v, __shfl_xor_sync(0xffffffffu, v, o));
    return v;
}
__device__ __forceinline__ float blockSum256(float v, float* sm) {
    int lane = threadIdx.x & 31, w = threadIdx.x >> 5;
    v = warpSum(v);
    if (lane == 0) sm[w] = v;
    __syncthreads();
    if (threadIdx.x == 0) {
        float s = 0.f;
#pragma unroll
        for (int i = 0; i < 8; i++) s += sm[i];
        sm[0] = s;
    }
    __syncthreads();
    float r = sm[0];
    __syncthreads();
    return r;
}
__device__ __forceinline__ float blockMax256(float v, float* sm) {
    int lane = threadIdx.x & 31, w = threadIdx.x >> 5;
    v = warpMax(v);
    if (lane == 0) sm[w] = v;
    __syncthreads();
    if (threadIdx.x == 0) {
        float s = sm[0];
#pragma unroll
        for (int i = 1; i < 8; i++) s = fmaxf(s, sm[i]);
        sm[0] = s;
    }
    __syncthreads();
    float r = sm[0];
    __syncthreads();
    return r;
}

__device__ __forceinline__ int bucketBase(int m) {
    return (m < NN) ? m * CCAP : TBASE + (m - NN) * TCAP;
}
__device__ __forceinline__ int bucketCap(int m) {
    return (m < NN) ? CCAP : TCAP;
}

// tf32 round of a float4 (RNA, same as wmma::__float_to_tf32 per element)
__device__ __forceinline__ float4 cvt4_tf32(float4 v) {
    v.x = wmma::__float_to_tf32(v.x);
    v.y = wmma::__float_to_tf32(v.y);
    v.z = wmma::__float_to_tf32(v.z);
    v.w = wmma::__float_to_tf32(v.w);
    return v;
}

// ---------------- structure build ----------------
__global__ void init_k() {
    int i = blockIdx.x * blockDim.x + threadIdx.x;
    int st = gridDim.x * blockDim.x;
    for (int j = i; j < MM; j += st) { g_col_fill[j] = 0; g_deg[j] = 0.f; }
    for (int j = i; j < NN; j += st) g_A[j] = 0.f;
    if (i == 0) { g_bar1 = 0; g_bar2 = 0; }
}

// warp per row; MLP=4 loads. Builds ordered row lists AND scatters nonzeros
// directly into the bucketed CSC (slot = atomicAdd on fill) in ONE pass over H.
__device__ __forceinline__ void scatterNZ(int m, int warp, float v,
                                          int* ri, float* rv, int pos) {
    ri[pos] = m; rv[pos] = v;
    atomicAdd(&g_deg[m], v);
    int p = atomicAdd(&g_col_fill[m], 1);
    if (p < bucketCap(m)) {
        int o = bucketBase(m) + p;
        g_col_idx[o] = warp;
        g_col_val[o] = v;
    }
}

__global__ void __launch_bounds__(256) build_rows(const float* __restrict__ H) {
    int warp = (blockIdx.x * blockDim.x + threadIdx.x) >> 5;
    if (warp >= NN) return;
    int lane = threadIdx.x & 31;
    const float4* row4 = (const float4*)(H + (size_t)warp * MM);  // 1025 float4
    int* ri = g_row_idx + (size_t)warp * RCAP;
    float* rv = g_row_val + (size_t)warp * RCAP;
    int base = 0;
#pragma unroll 1
    for (int it = 0; it < 8; it++) {
        float4 v[4];
#pragma unroll
        for (int sub = 0; sub < 4; sub++)
            v[sub] = row4[it * 128 + sub * 32 + lane];
#pragma unroll
        for (int sub = 0; sub < 4; sub++) {
            int colbase = (it * 128 + sub * 32 + lane) * 4;
            int c0 = v[sub].x != 0.f, c1 = v[sub].y != 0.f;
            int c2 = v[sub].z != 0.f, c3 = v[sub].w != 0.f;
            int cnt = c0 + c1 + c2 + c3;
            int inc = cnt;
#pragma unroll
            for (int o = 1; o < 32; o <<= 1) {
                int t = __shfl_up_sync(0xffffffffu, inc, o);
                if (lane >= o) inc += t;
            }
            int tot = __shfl_sync(0xffffffffu, inc, 31);
            int pos = base + inc - cnt;
            if (c0) { scatterNZ(colbase,     warp, v[sub].x, ri, rv, pos); pos++; }
            if (c1) { scatterNZ(colbase + 1, warp, v[sub].y, ri, rv, pos); pos++; }
            if (c2) { scatterNZ(colbase + 2, warp, v[sub].z, ri, rv, pos); pos++; }
            if (c3) { scatterNZ(colbase + 3, warp, v[sub].w, ri, rv, pos); pos++; }
            base += tot;
        }
    }
    // tail: float4 #1024 covers cols 4096..4099 (lane 0 only)
    {
        float4 v = (lane == 0) ? row4[1024] : make_float4(0.f, 0.f, 0.f, 0.f);
        int colbase = 4096;
        int c0 = (lane == 0) && (v.x != 0.f), c1 = (lane == 0) && (v.y != 0.f);
        int c2 = (lane == 0) && (v.z != 0.f), c3 = (lane == 0) && (v.w != 0.f);
        int cnt = c0 + c1 + c2 + c3;
        int inc = cnt;
#pragma unroll
        for (int o = 1; o < 32; o <<= 1) {
            int t = __shfl_up_sync(0xffffffffu, inc, o);
            if (lane >= o) inc += t;
        }
        int tot = __shfl_sync(0xffffffffu, inc, 31);
        int pos = base + inc - cnt;
        if (c0) { scatterNZ(colbase,     warp, v.x, ri, rv, pos); pos++; }
        if (c1) { scatterNZ(colbase + 1, warp, v.y, ri, rv, pos); pos++; }
        if (c2) { scatterNZ(colbase + 2, warp, v.z, ri, rv, pos); pos++; }
        if (c3) { scatterNZ(colbase + 3, warp, v.w, ri, rv, pos); pos++; }
        base += tot;
    }
    if (lane == 0) g_row_cnt[warp] = base;
}

// ---------------- per-layer kernels ----------------
__global__ void ln_rows(const float* __restrict__ X, float* __restrict__ O,
                        const float* __restrict__ g, const float* __restrict__ b) {
    int warp = (blockIdx.x * blockDim.x + threadIdx.x) >> 5;
    if (warp >= NN) return;
    int lane = threadIdx.x & 31;
    const float4* x4 = (const float4*)(X + (size_t)warp * DD);
    float4 v0 = x4[lane], v1 = x4[lane + 32];
    float s = v0.x + v0.y + v0.z + v0.w + v1.x + v1.y + v1.z + v1.w;
    s = warpSum(s);
    float mean = s * (1.f / 256.f);
    float c0x = v0.x - mean, c0y = v0.y - mean, c0z = v0.z - mean, c0w = v0.w - mean;
    float c1x = v1.x - mean, c1y = v1.y - mean, c1z = v1.z - mean, c1w = v1.w - mean;
    float ss = c0x*c0x + c0y*c0y + c0z*c0z + c0w*c0w + c1x*c1x + c1y*c1y + c1z*c1z + c1w*c1w;
    ss = warpSum(ss);
    float rs = rsqrtf(ss * (1.f / 256.f) + 1e-5f);
    const float4* g4 = (const float4*)g;
    const float4* b4 = (const float4*)b;
    float4 G0 = g4[lane], G1 = g4[lane + 32], B0 = b4[lane], B1 = b4[lane + 32];
    float4* o4 = (float4*)(O + (size_t)warp * DD);
    o4[lane]      = make_float4(c0x*rs*G0.x + B0.x, c0y*rs*G0.y + B0.y,
                                c0z*rs*G0.z + B0.z, c0w*rs*G0.w + B0.w);
    o4[lane + 32] = make_float4(c1x*rs*G1.x + B1.x, c1y*rs*G1.y + B1.y,
                                c1z*rs*G1.z + B1.z, c1w*rs*G1.w + B1.w);
}

// blocks [0,128): dense tail partials (long poles -> scheduled FIRST)
// blocks [128,NN+128): sparse edge gather + LN -> g_En  (bucketed CSC)
__global__ void __launch_bounds__(256) egather_all(const float* __restrict__ X,
        const float* __restrict__ g, const float* __restrict__ b) {
    __shared__ int sidx[CCAP];
    __shared__ float sval[CCAP];
    __shared__ float sm[8];
    int bid = blockIdx.x, d = threadIdx.x;
    if (bid >= 128) {
        int m = bid - 128;
        int p0 = m * CCAP;
        int cnt = min(g_col_fill[m], CCAP);
        if (d < cnt) { sidx[d] = g_col_idx[p0 + d]; sval[d] = g_col_val[p0 + d]; }
        __syncthreads();
        float a0 = 0.f, a1 = 0.f, a2 = 0.f, a3 = 0.f;
        int j = 0;
        for (; j + 4 <= cnt; j += 4) {
            int n0 = sidx[j], n1 = sidx[j+1], n2 = sidx[j+2], n3 = sidx[j+3];
            float x0 = X[(size_t)n0 * DD + d], x1 = X[(size_t)n1 * DD + d];
            float x2 = X[(size_t)n2 * DD + d], x3 = X[(size_t)n3 * DD + d];
            a0 = fmaf(sval[j],   x0, a0); a1 = fmaf(sval[j+1], x1, a1);
            a2 = fmaf(sval[j+2], x2, a2); a3 = fmaf(sval[j+3], x3, a3);
        }
        for (; j < cnt; j++) a0 = fmaf(sval[j], X[(size_t)sidx[j] * DD + d], a0);
        float acc = ((a0 + a1) + (a2 + a3)) / g_deg[m];
        float mean = blockSum256(acc, sm) * (1.f / 256.f);
        float c = acc - mean;
        float var = blockSum256(c * c, sm) * (1.f / 256.f);
        float rs = rsqrtf(var + 1e-5f);
        g_En[(size_t)m * DD + d] = c * rs * g[d] + b[d];
    } else {
        int t = bid;
        int e = t >> 5, slice = t & 31;
        int m = NN + e;
        int p0 = TBASE + e * TCAP;
        int cnt = min(g_col_fill[m], TCAP);
        int per = (cnt + 31) / 32;
        int s0 = p0 + slice * per;
        int s1 = min(s0 + per, p0 + cnt);
        float a0 = 0.f, a1 = 0.f, a2 = 0.f, a3 = 0.f;
        int p = s0;
        for (; p + 4 <= s1; p += 4) {
            int n0 = g_col_idx[p], n1 = g_col_idx[p+1], n2 = g_col_idx[p+2], n3 = g_col_idx[p+3];
            float w0 = g_col_val[p], w1 = g_col_val[p+1], w2 = g_col_val[p+2], w3 = g_col_val[p+3];
            a0 = fmaf(w0, X[(size_t)n0 * DD + d], a0);
            a1 = fmaf(w1, X[(size_t)n1 * DD + d], a1);
            a2 = fmaf(w2, X[(size_t)n2 * DD + d], a2);
            a3 = fmaf(w3, X[(size_t)n3 * DD + d], a3);
        }
        for (; p < s1; p++) a0 = fmaf(g_col_val[p], X[(size_t)g_col_idx[p] * DD + d], a0);
        g_epart[(size_t)(e * 32 + slice) * DD + d] = (a0 + a1) + (a2 + a3);
    }
}

// 32 blocks: each redundantly reduces dense-tail partials + LN in smem, then
// computes its share of the tail k projections.
__global__ void __launch_bounds__(256) ktail_fin(
        const float* __restrict__ Wkt, const float* __restrict__ bkt,
        const float* __restrict__ Wks, const float* __restrict__ bks,
        const float* __restrict__ g, const float* __restrict__ b) {
    __shared__ __align__(16) float e[4][DD];
    __shared__ float smr[8];
    int tid = threadIdx.x;
#pragma unroll
    for (int r = 0; r < 4; r++) {
        float acc = 0.f;
#pragma unroll
        for (int s = 0; s < 32; s++) acc += g_epart[(size_t)(r * 32 + s) * DD + tid];
        acc /= g_deg[NN + r];
        float mean = blockSum256(acc, smr) * (1.f / 256.f);
        float c = acc - mean;
        float var = blockSum256(c * c, smr) * (1.f / 256.f);
        float rs = rsqrtf(var + 1e-5f);
        e[r][tid] = c * rs * g[tid] + b[tid];
    }
    __syncthreads();
    int w = tid >> 5, lane = tid & 31;
    int gw = blockIdx.x * 8 + w;   // 0..255
    for (int t = gw; t < 4 * DD; t += 256) {
        int r = t >> 8, o = t & 255;
        const float* wrow = ((r < 3) ? Wkt : Wks) + (size_t)o * DD;
        const float4* w4 = (const float4*)wrow;
        const float4* e4 = (const float4*)e[r];
        float4 a = w4[lane], bb = e4[lane];
        float acc = a.x*bb.x + a.y*bb.y + a.z*bb.z + a.w*bb.w;
        float4 a2 = w4[lane + 32], b2 = e4[lane + 32];
        acc += a2.x*b2.x + a2.y*b2.y + a2.z*b2.z + a2.w*b2.w;
        acc = warpSum(acc);
        if (lane == 0) g_k[(size_t)(NN + r) * DD + o] = acc + ((r < 3) ? bkt[o] : bks[o]);
    }
}

// ---------------- tf32 tensor-core GEMM (128x64 tile, ASTRIDE 36, cvt@stage) ----
#define ASTRIDE 36
#define CSTRIDE 68
template <int EPI>
__global__ void __launch_bounds__(256) gemm_tc(const float* __restrict__ A,
        const float* __restrict__ W, const float* __restrict__ bias,
        float* __restrict__ C, const float* __restrict__ R) {
    __shared__ __align__(16) float sm[128 * CSTRIDE];   // 34.8 KB (epilogue needs 128x68)
    float* As = sm;                    // 128 x ASTRIDE
    float* Ws = sm + 128 * ASTRIDE;    // 64 x ASTRIDE
    int tid = threadIdx.x;
    int wid = tid >> 5;
    int wr = wid >> 1;      // 0..3
    int wc = wid & 1;       // 0..1
    int rowBase = blockIdx.x * 128;
    int colBase = blockIdx.y * 64;

    wmma::fragment<wmma::accumulator, 16, 16, 8, float> acc[2][2];
#pragma unroll
    for (int i = 0; i < 2; i++)
#pragma unroll
        for (int j = 0; j < 2; j++) wmma::fill_fragment(acc[i][j], 0.f);

#pragma unroll 1
    for (int k0 = 0; k0 < 256; k0 += 32) {
        // stage A tile 128x32 (converted to tf32 bits)
#pragma unroll
        for (int i = 0; i < 4; i++) {
            int idx = tid + i * 256;
            int row = idx >> 3;
            int c4 = (idx & 7) * 4;
            float4 v = *(const float4*)(A + (size_t)(rowBase + row) * DD + k0 + c4);
            *(float4*)&As[row * ASTRIDE + c4] = cvt4_tf32(v);
        }
        // stage W tile 64x32 (converted to tf32 bits)
#pragma unroll
        for (int i = 0; i < 2; i++) {
            int idx = tid + i * 256;
            int row = idx >> 3;
            int c4 = (idx & 7) * 4;
            float4 v = *(const float4*)(W + (size_t)(colBase + row) * DD + k0 + c4);
            *(float4*)&Ws[row * ASTRIDE + c4] = cvt4_tf32(v);
        }
        __syncthreads();
#pragma unroll
        for (int kk = 0; kk < 32; kk += 8) {
            wmma::fragment<wmma::matrix_a, 16, 16, 8, wmma::precision::tf32, wmma::row_major> a[2];
            wmma::fragment<wmma::matrix_b, 16, 16, 8, wmma::precision::tf32, wmma::col_major> b[2];
            wmma::load_matrix_sync(a[0], &As[(wr * 32) * ASTRIDE + kk], ASTRIDE);
            wmma::load_matrix_sync(a[1], &As[(wr * 32 + 16) * ASTRIDE + kk], ASTRIDE);
            wmma::load_matrix_sync(b[0], &Ws[(wc * 32) * ASTRIDE + kk], ASTRIDE);
            wmma::load_matrix_sync(b[1], &Ws[(wc * 32 + 16) * ASTRIDE + kk], ASTRIDE);
#pragma unroll
            for (int i = 0; i < 2; i++)
#pragma unroll
                for (int j = 0; j < 2; j++)
                    wmma::mma_sync(acc[i][j], a[i], b[j], acc[i][j]);
        }
        __syncthreads();
    }
#pragma unroll
    for (int i = 0; i < 2; i++)
#pragma unroll
        for (int j = 0; j < 2; j++)
            wmma::store_matrix_sync(&sm[(wr * 32 + i * 16) * CSTRIDE + wc * 32 + j * 16],
                                    acc[i][j], CSTRIDE, wmma::mem_row_major);
    __syncthreads();

#pragma unroll
    for (int e4 = 0; e4 < 8; e4++) {
        int linear = tid + e4 * 256;      // 0..2047 float4 slots
        int row = linear >> 4;            // 16 float4 per 64-wide row
        int col = (linear & 15) * 4;
        float4 v = *(float4*)&sm[row * CSTRIDE + col];
        float4 bv = *(const float4*)(bias + colBase + col);
        v.x += bv.x; v.y += bv.y; v.z += bv.z; v.w += bv.w;
        int grow = rowBase + row;
        if (EPI == 1) {
            float4 rv = *(const float4*)(R + (size_t)grow * DD + colBase + col);
            v.x = fmaxf(v.x, 0.f) * 0.5f + 0.5f * rv.x;
            v.y = fmaxf(v.y, 0.f) * 0.5f + 0.5f * rv.y;
            v.z = fmaxf(v.z, 0.f) * 0.5f + 0.5f * rv.z;
            v.w = fmaxf(v.w, 0.f) * 0.5f + 0.5f * rv.w;
        }
        *(float4*)(C + (size_t)grow * DD + colBase + col) = v;
    }
}

// Fused gated-attention GEMM: tanh & sigmoid branches for a 128x64 tile,
// reduced through cw directly into g_A via atomics. cvt@stage.
__global__ void __launch_bounds__(256) gemm_gated(const float* __restrict__ A,
        const float* __restrict__ Wa, const float* __restrict__ ba,
        const float* __restrict__ Wb, const float* __restrict__ bb_,
        const float* __restrict__ cw) {
    __shared__ __align__(16) float sm[10240];
    float* As  = sm;           // 128 x ASTRIDE (4608)
    float* Was = sm + 5120;    // 64 x ASTRIDE (2304)
    float* Wbs = sm + 7680;    // 64 x ASTRIDE (2304)
    int tid = threadIdx.x;
    int wid = tid >> 5;
    int wr = wid >> 1;
    int wc = wid & 1;
    int rowBase = blockIdx.x * 128;
    int colBase = blockIdx.y * 64;

    wmma::fragment<wmma::accumulator, 16, 16, 8, float> accA[2][2], accB[2][2];
#pragma unroll
    for (int i = 0; i < 2; i++)
#pragma unroll
        for (int j = 0; j < 2; j++) {
            wmma::fill_fragment(accA[i][j], 0.f);
            wmma::fill_fragment(accB[i][j], 0.f);
        }

#pragma unroll 1
    for (int k0 = 0; k0 < 256; k0 += 32) {
#pragma unroll
        for (int i = 0; i < 4; i++) {
            int idx = tid + i * 256;
            int row = idx >> 3;
            int c4 = (idx & 7) * 4;
            float4 v = *(const float4*)(A + (size_t)(rowBase + row) * DD + k0 + c4);
            *(float4*)&As[row * ASTRIDE + c4] = cvt4_tf32(v);
        }
#pragma unroll
        for (int i = 0; i < 2; i++) {
            int idx = tid + i * 256;
            int row = idx >> 3;
            int c4 = (idx & 7) * 4;
            float4 va = *(const float4*)(Wa + (size_t)(colBase + row) * DD + k0 + c4);
            float4 vb = *(const float4*)(Wb + (size_t)(colBase + row) * DD + k0 + c4);
            *(float4*)&Was[row * ASTRIDE + c4] = cvt4_tf32(va);
            *(float4*)&Wbs[row * ASTRIDE + c4] = cvt4_tf32(vb);
        }
        __syncthreads();
#pragma unroll
        for (int kk = 0; kk < 32; kk += 8) {
            wmma::fragment<wmma::matrix_a, 16, 16, 8, wmma::precision::tf32, wmma::row_major> a[2];
            wmma::fragment<wmma::matrix_b, 16, 16, 8, wmma::precision::tf32, wmma::col_major> bA[2], bB[2];
            wmma::load_matrix_sync(a[0], &As[(wr * 32) * ASTRIDE + kk], ASTRIDE);
            wmma::load_matrix_sync(a[1], &As[(wr * 32 + 16) * ASTRIDE + kk], ASTRIDE);
            wmma::load_matrix_sync(bA[0], &Was[(wc * 32) * ASTRIDE + kk], ASTRIDE);
            wmma::load_matrix_sync(bA[1], &Was[(wc * 32 + 16) * ASTRIDE + kk], ASTRIDE);
            wmma::load_matrix_sync(bB[0], &Wbs[(wc * 32) * ASTRIDE + kk], ASTRIDE);
            wmma::load_matrix_sync(bB[1], &Wbs[(wc * 32 + 16) * ASTRIDE + kk], ASTRIDE);
#pragma unroll
            for (int i = 0; i < 2; i++)
#pragma unroll
                for (int j = 0; j < 2; j++) {
                    wmma::mma_sync(accA[i][j], a[i], bA[j], accA[i][j]);
                    wmma::mma_sync(accB[i][j], a[i], bB[j], accB[i][j]);
                }
        }
        __syncthreads();
    }
#pragma unroll
    for (int i = 0; i < 2; i++)
#pragma unroll
        for (int j = 0; j < 2; j++)
            wmma::store_matrix_sync(&sm[(wr * 32 + i * 16) * CSTRIDE + wc * 32 + j * 16],
                                    accA[i][j], CSTRIDE, wmma::mem_row_major);
    __syncthreads();
    float av[8][4];
#pragma unroll
    for (int e4 = 0; e4 < 8; e4++) {
        int linear = tid + e4 * 256;
        int row = linear >> 4;
        int col = (linear & 15) * 4;
        float4 v = *(float4*)&sm[row * CSTRIDE + col];
        float4 bv = *(const float4*)(ba + colBase + col);
        av[e4][0] = tanhf(v.x + bv.x); av[e4][1] = tanhf(v.y + bv.y);
        av[e4][2] = tanhf(v.z + bv.z); av[e4][3] = tanhf(v.w + bv.w);
    }
    __syncthreads();
#pragma unroll
    for (int i = 0; i < 2; i++)
#pragma unroll
        for (int j = 0; j < 2; j++)
            wmma::store_matrix_sync(&sm[(wr * 32 + i * 16) * CSTRIDE + wc * 32 + j * 16],
                                    accB[i][j], CSTRIDE, wmma::mem_row_major);
    __syncthreads();
#pragma unroll
    for (int e4 = 0; e4 < 8; e4++) {
        int linear = tid + e4 * 256;
        int row = linear >> 4;
        int col = (linear & 15) * 4;
        float4 v = *(float4*)&sm[row * CSTRIDE + col];
        float4 bv = *(const float4*)(bb_ + colBase + col);
        float4 cv = *(const float4*)(cw + colBase + col);
        float s0 = 1.f / (1.f + __expf(-(v.x + bv.x)));
        float s1 = 1.f / (1.f + __expf(-(v.y + bv.y)));
        float s2 = 1.f / (1.f + __expf(-(v.z + bv.z)));
        float s3 = 1.f / (1.f + __expf(-(v.w + bv.w)));
        float partial = av[e4][0]*s0*cv.x + av[e4][1]*s1*cv.y
                      + av[e4][2]*s2*cv.z + av[e4][3]*s3*cv.w;
#pragma unroll
        for (int o = 8; o; o >>= 1)
            partial += __shfl_down_sync(0xffffffffu, partial, o, 16);
        if ((tid & 15) == 0) atomicAdd(&g_A[rowBase + row], partial);
    }
}

// sparse masked MHA; block per node, warp per head. Plain softmax (bounded scores).
__global__ void __launch_bounds__(256) attn_k() {
    int n = blockIdx.x;
    int tid = threadIdx.x;
    int h = tid >> 5, lane = tid & 31;
    __shared__ int sidx[RCAP];
    int cnt = g_row_cnt[n];
    if (tid < cnt) sidx[tid] = g_row_idx[(size_t)n * RCAP + tid];
    __syncthreads();
    int off = h * 32 + lane;
    float qv = g_q[(size_t)n * DD + off];
    float s = 0.f, acc = 0.f;
    const float sc = 0.17677669529663687f;  // 1/sqrt(32)
    for (int j0 = 0; j0 < cnt; j0 += 4) {
        int c = cnt - j0;
        float kv0 = g_k[(size_t)sidx[j0] * DD + off];
        float kv1 = (c > 1) ? g_k[(size_t)sidx[j0+1] * DD + off] : 0.f;
        float kv2 = (c > 2) ? g_k[(size_t)sidx[j0+2] * DD + off] : 0.f;
        float kv3 = (c > 3) ? g_k[(size_t)sidx[j0+3] * DD + off] : 0.f;
        float p0 = qv * kv0, p1 = qv * kv1, p2 = qv * kv2, p3 = qv * kv3;
#pragma unroll
        for (int o = 16; o; o >>= 1) {
            p0 += __shfl_xor_sync(0xffffffffu, p0, o);
            p1 += __shfl_xor_sync(0xffffffffu, p1, o);
            p2 += __shfl_xor_sync(0xffffffffu, p2, o);
            p3 += __shfl_xor_sync(0xffffffffu, p3, o);
        }
        float e0 = __expf(p0 * sc);
        float e1 = __expf(p1 * sc);
        float e2 = __expf(p2 * sc);
        float e3 = __expf(p3 * sc);
        s += e0;               acc = fmaf(e0, kv0, acc);
        if (c > 1) { s += e1;  acc = fmaf(e1, kv1, acc); }
        if (c > 2) { s += e2;  acc = fmaf(e2, kv2, acc); }
        if (c > 3) { s += e3;  acc = fmaf(e3, kv3, acc); }
    }
    g_af[(size_t)n * DD + off] = acc / s;
}

// ---------------- fused pooling head (64 blocks, software grid barrier) ---------
__device__ __forceinline__ void gridBar(int* bar, int expected) {
    __syncthreads();
    if (threadIdx.x == 0) {
        __threadfence();
        atomicAdd(bar, 1);
        while (atomicAdd(bar, 0) < expected) { }
    }
    __syncthreads();
}

__global__ void __launch_bounds__(256) pool_all(const float* __restrict__ F,
        const float* __restrict__ ow, const float* __restrict__ ob,
        float* __restrict__ out) {
    __shared__ float sm[8];
    int b = blockIdx.x, tid = threadIdx.x;
    int n0 = b * 64;
    float v = (tid < 64) ? g_A[n0 + tid] : -1e30f;
    float bm = blockMax256(v, sm);
    if (tid == 0) g_pmax[b] = bm;
    gridBar(&g_bar1, 64);
    float pm = (tid < 64) ? g_pmax[tid] : -1e30f;
    float gmax = blockMax256(pm, sm);
    float acc = 0.f;
    for (int j = 0; j < 64; j++) {
        float w = __expf(g_A[n0 + j] - gmax);
        acc = fmaf(w, F[(size_t)(n0 + j) * DD + tid], acc);
    }
    g_part[(size_t)b * DD + tid] = acc;
    float e = (tid < 64) ? __expf(g_A[n0 + tid] - gmax) : 0.f;
    float ps = blockSum256(e, sm);
    if (tid == 0) { g_psum[b] = ps; __threadfence(); }
    gridBar(&g_bar2, 64);
    if (b == 0) {
        __shared__ float pooled[DD];
        float a = 0.f;
        for (int q = 0; q < 64; q++) a += g_part[(size_t)q * DD + tid];
        float pv = (tid < 64) ? g_psum[tid] : 0.f;
        float tot = blockSum256(pv, sm);
        pooled[tid] = a / tot;
        __syncthreads();
        int h = tid >> 5, lane = tid & 31;
        if (h < 4) {
            const float* w = ow + (size_t)h * DD;
            float o = 0.f;
            for (int k2 = lane; k2 < DD; k2 += 32) o = fmaf(pooled[k2], w[k2], o);
            o = warpSum(o);
            if (lane == 0) out[h] = o + ob[h];
        }
    }
}

// ---------------- host orchestration (stream-forked graph) ----------------
struct DevPtrs {
    float *Xn, *En, *q, *k, *af, *X1, *X2;
};

static DevPtrs s_p = {};
static cudaStream_t s_side = 0;
static cudaEvent_t s_evStart, s_evEg1, s_evQK1, s_evX1, s_evEg2, s_evQK2;
static bool s_init = false;

static void one_time_init() {
    if (s_init) return;
    cudaGetSymbolAddress((void**)&s_p.Xn, g_Xn);
    cudaGetSymbolAddress((void**)&s_p.En, g_En);
    cudaGetSymbolAddress((void**)&s_p.q,  g_q);
    cudaGetSymbolAddress((void**)&s_p.k,  g_k);
    cudaGetSymbolAddress((void**)&s_p.af, g_af);
    cudaGetSymbolAddress((void**)&s_p.X1, g_X1);
    cudaGetSymbolAddress((void**)&s_p.X2, g_X2);
    cudaStreamCreateWithFlags(&s_side, cudaStreamNonBlocking);
    cudaEventCreateWithFlags(&s_evStart, cudaEventDisableTiming);
    cudaEventCreateWithFlags(&s_evEg1,   cudaEventDisableTiming);
    cudaEventCreateWithFlags(&s_evQK1,   cudaEventDisableTiming);
    cudaEventCreateWithFlags(&s_evX1,    cudaEventDisableTiming);
    cudaEventCreateWithFlags(&s_evEg2,   cudaEventDisableTiming);
    cudaEventCreateWithFlags(&s_evQK2,   cudaEventDisableTiming);
    s_init = true;
}

extern "C" void kernel_launch(void* const* d_in, const int* in_sizes, int n_in,
                              void* d_out, int out_size) {
    (void)in_sizes; (void)n_in; (void)out_size;
    const float* X     = (const float*)d_in[0];
    const float* H     = (const float*)d_in[1];
    const float* Wq_w  = (const float*)d_in[2];
    const float* Wq_b  = (const float*)d_in[3];
    const float* Wkn_w = (const float*)d_in[4];
    const float* Wkn_b = (const float*)d_in[5];
    const float* Wkt_w = (const float*)d_in[6];
    const float* Wkt_b = (const float*)d_in[7];
    const float* Wks_w = (const float*)d_in[8];
    const float* Wks_b = (const float*)d_in[9];
    const float* fc_w  = (const float*)d_in[10];
    const float* fc_b  = (const float*)d_in[11];
    const float* ln_g  = (const float*)d_in[12];
    const float* ln_b  = (const float*)d_in[13];
    const float* aw    = (const float*)d_in[14];
    const float* ab    = (const float*)d_in[15];
    const float* bw    = (const float*)d_in[16];
    const float* bb    = (const float*)d_in[17];
    const float* cw    = (const float*)d_in[18];
    const float* out_w = (const float*)d_in[20];
    const float* out_b = (const float*)d_in[21];
    float* out = (float*)d_out;

    one_time_init();
    const DevPtrs& p = s_p;
    const int WOFF = DD * DD;
    dim3 grid(32, 4);   // 128x64 tiles -> 128 blocks

    // fork side stream off the capture-origin (default) stream
    cudaEventRecord(s_evStart, 0);
    cudaStreamWaitEvent(s_side, s_evStart, 0);

    // ---- main: structure build (single pass: row lists + bucketed CSC) ----
    init_k<<<32, 256>>>();
    build_rows<<<512, 256>>>(H);

    // ---- side: layer-1 q path (needs only X) ----
    ln_rows<<<512, 256, 0, s_side>>>(X, p.Xn, ln_g, ln_b);
    gemm_tc<0><<<grid, 256, 0, s_side>>>(p.Xn, Wq_w, Wq_b, p.q, nullptr);

    // ---- main: layer-1 edge path ----
    egather_all<<<NN + 128, 256>>>(X, ln_g, ln_b);
    cudaEventRecord(s_evEg1, 0);
    gemm_tc<0><<<grid, 256>>>(p.En, Wkn_w, Wkn_b, p.k, nullptr);

    // ---- side: ktail after egather partials ----
    cudaStreamWaitEvent(s_side, s_evEg1, 0);
    ktail_fin<<<32, 256, 0, s_side>>>(Wkt_w, Wkt_b, Wks_w, Wks_b, ln_g, ln_b);
    cudaEventRecord(s_evQK1, s_side);

    // ---- main: join, attention, fc ----
    cudaStreamWaitEvent(0, s_evQK1, 0);
    attn_k<<<NN, 256>>>();
    gemm_tc<1><<<grid, 256>>>(p.af, fc_w, fc_b, p.X1, X);
    cudaEventRecord(s_evX1, 0);

    // ---- side: layer-2 q path ----
    cudaStreamWaitEvent(s_side, s_evX1, 0);
    ln_rows<<<512, 256, 0, s_side>>>(p.X1, p.Xn, ln_g + DD, ln_b + DD);
    gemm_tc<0><<<grid, 256, 0, s_side>>>(p.Xn, Wq_w + WOFF, Wq_b + DD, p.q, nullptr);

    // ---- main: layer-2 edge path ----
    egather_all<<<NN + 128, 256>>>(p.X1, ln_g + DD, ln_b + DD);
    cudaEventRecord(s_evEg2, 0);
    gemm_tc<0><<<grid, 256>>>(p.En, Wkn_w + WOFF, Wkn_b + DD, p.k, nullptr);

    cudaStreamWaitEvent(s_side, s_evEg2, 0);
    ktail_fin<<<32, 256, 0, s_side>>>(Wkt_w + WOFF, Wkt_b + DD,
                                      Wks_w + WOFF, Wks_b + DD,
                                      ln_g + DD, ln_b + DD);
    cudaEventRecord(s_evQK2, s_side);

    cudaStreamWaitEvent(0, s_evQK2, 0);
    attn_k<<<NN, 256>>>();
    gemm_tc<1><<<grid, 256>>>(p.af, fc_w + WOFF, fc_b + DD, p.X2, p.X1);

    // ---- pooling head ----
    gemm_gated<<<dim3(32, 4), 256>>>(p.X2, aw, ab, bw, bb, cw);
    pool_all<<<64, 256>>>(p.X2, out_w, out_b, out);
}